// round 14
// baseline (speedup 1.0000x reference)
#include <cuda_runtime.h>
#include <cuda_fp16.h>
#include <cstdint>

// ---------------- problem constants ----------------
#define NN      200000
#define NE      1600000
#define NG      5000
#define FDIM    128
#define MAXH    3
#define MAXM    (MAXH*FDIM)   // 384
#define ETOT    (NE + NN)
#define SCAN_B  1024
#define SCAN_NB ((NN + SCAN_B - 1) / SCAN_B)   // 196

// ---------------- scratch ----------------
__device__ __half g_h   [(size_t)NN * MAXM];   // GEMM output features (fp16)
__device__ __half g_feat[(size_t)NN * MAXM];   // layer input features (fp16)
__device__ __half g_xh  [(size_t)NN * FDIM];   // fp16 copy of input x
__device__ __half g_wt  [3 * 384 * 384];       // transposed fp16 weights
__device__ float g_als [(size_t)NN * MAXH];
__device__ float g_ald [(size_t)NN * MAXH];
__device__ float g_pool[(size_t)NG * FDIM];
__device__ int   g_cnt [NG];
__device__ int   g_deg [NN];
__device__ int   g_rowptr[NN + 1];
__device__ int   g_woff[NN];
__device__ int   g_bsum[256];
__device__ int   g_csrc[ETOT];

// ---------------- helpers ----------------
__device__ __forceinline__ float lrelu(float v) { return v > 0.0f ? v : 0.2f * v; }

__device__ __forceinline__ void mma_f16(float* d, const unsigned* a, const unsigned* b) {
    asm volatile(
        "mma.sync.aligned.m16n8k16.row.col.f32.f16.f16.f32 "
        "{%0,%1,%2,%3}, {%4,%5,%6,%7}, {%8,%9}, {%0,%1,%2,%3};"
        : "+f"(d[0]), "+f"(d[1]), "+f"(d[2]), "+f"(d[3])
        : "r"(a[0]), "r"(a[1]), "r"(a[2]), "r"(a[3]), "r"(b[0]), "r"(b[1]));
}

__device__ __forceinline__ void ldsm4(unsigned& r0, unsigned& r1, unsigned& r2, unsigned& r3,
                                      unsigned addr) {
    asm volatile("ldmatrix.sync.aligned.m8n8.x4.shared.b16 {%0,%1,%2,%3}, [%4];"
                 : "=r"(r0), "=r"(r1), "=r"(r2), "=r"(r3) : "r"(addr));
}

#define CP_ASYNC16(saddr, gptr) \
    asm volatile("cp.async.cg.shared.global [%0], [%1], 16;" :: "r"(saddr), "l"(gptr))
#define CP_COMMIT() asm volatile("cp.async.commit_group;")
#define CP_WAIT2()  asm volatile("cp.async.wait_group 2;")

// ---------------- small utility kernels ----------------
__global__ void zero_f(float* p, size_t n) {
    size_t i = (size_t)blockIdx.x * blockDim.x + threadIdx.x;
    size_t stride = (size_t)gridDim.x * blockDim.x;
    for (; i < n; i += stride) p[i] = 0.0f;
}
__global__ void zero_i(int* p, size_t n) {
    size_t i = (size_t)blockIdx.x * blockDim.x + threadIdx.x;
    size_t stride = (size_t)gridDim.x * blockDim.x;
    for (; i < n; i += stride) p[i] = 0;
}
__global__ void cvt_x_kernel(const float* __restrict__ x, __half* __restrict__ xh, size_t n2) {
    size_t i = (size_t)blockIdx.x * blockDim.x + threadIdx.x;
    size_t stride = (size_t)gridDim.x * blockDim.x;
    for (; i < n2; i += stride) {
        float2 v = ((const float2*)x)[i];
        ((__half2*)xh)[i] = __floats2half2_rn(v.x, v.y);
    }
}
__global__ void cvt_w_kernel(const float* __restrict__ W, __half* __restrict__ Wt, int K, int M) {
    int idx = blockIdx.x * blockDim.x + threadIdx.x;
    if (idx >= K * M) return;
    int k = idx / M, m = idx - k * M;
    Wt[(size_t)m * K + k] = __float2half_rn(W[idx]);
}

// ================= CSR construction (by destination) =================
__global__ void deg_kernel(const int* __restrict__ dsts, int E, int Nn, int* __restrict__ deg) {
    int e = blockIdx.x * blockDim.x + threadIdx.x;
    int Et = E + Nn;
    if (e >= Et) return;
    int d = (e < E) ? dsts[e] : (e - E);
    atomicAdd(&deg[d], 1);
}

__global__ void scan1_kernel(const int* __restrict__ deg, int* __restrict__ excl,
                             int* __restrict__ bsum, int n) {
    __shared__ int sm[SCAN_B];
    int t = threadIdx.x;
    int gid = blockIdx.x * SCAN_B + t;
    int v = (gid < n) ? deg[gid] : 0;
    sm[t] = v;
    __syncthreads();
#pragma unroll
    for (int o = 1; o < SCAN_B; o <<= 1) {
        int u = (t >= o) ? sm[t - o] : 0;
        __syncthreads();
        sm[t] += u;
        __syncthreads();
    }
    if (gid < n) excl[gid] = sm[t] - v;
    if (t == SCAN_B - 1) bsum[blockIdx.x] = sm[t];
}

__global__ void scan2_kernel(int* __restrict__ bsum, int nb) {
    __shared__ int sm[256];
    int t = threadIdx.x;
    int v = (t < nb) ? bsum[t] : 0;
    sm[t] = v;
    __syncthreads();
#pragma unroll
    for (int o = 1; o < 256; o <<= 1) {
        int u = (t >= o) ? sm[t - o] : 0;
        __syncthreads();
        sm[t] += u;
        __syncthreads();
    }
    if (t < nb) bsum[t] = sm[t] - v;
}

__global__ void scan3_kernel(int* __restrict__ rowptr, int* __restrict__ woff,
                             const int* __restrict__ bsum, int n, int Et) {
    int gid = blockIdx.x * SCAN_B + threadIdx.x;
    if (gid < n) {
        int v = rowptr[gid] + bsum[gid >> 10];
        rowptr[gid] = v;
        woff[gid] = v;
    }
    if (gid == 0) rowptr[n] = Et;
}

__global__ void scatter_kernel(const int* __restrict__ srcs, const int* __restrict__ dsts,
                               int E, int Nn, int* __restrict__ woff, int* __restrict__ csrc) {
    int e = blockIdx.x * blockDim.x + threadIdx.x;
    int Et = E + Nn;
    if (e >= Et) return;
    int s, d;
    if (e < E) { s = srcs[e]; d = dsts[e]; }
    else       { s = d = e - E; }
    int pos = atomicAdd(&woff[d], 1);
    csrc[pos] = s;
}

// ================= tensor-core GEMM: fp16, 4-stage cp.async pipeline ===========
#define GBM 128
#define GBN 128
#define TST 20
#define STAGE_BYTES (GBM * TST * 4)   // 10240
#define NSTAGE 4
#define GEMM_SMEM (NSTAGE * STAGE_BYTES * 2)   // 81920

__global__ __launch_bounds__(256, 2) void gemm_fp16_kernel(const __half* __restrict__ A,
                                                           const __half* __restrict__ Wt,
                                                           __half* __restrict__ C,
                                                           int Nrows, int K, int M) {
    extern __shared__ unsigned smem_dyn[];

    const int bm = blockIdx.y * GBM;
    const int bn = blockIdx.x * GBN;
    const int t  = threadIdx.x;
    const int w  = t >> 5;
    const int l  = t & 31;
    const int g  = l >> 2;
    const int tg = l & 3;
    const int mw = (w & 1) * 64;
    const int nw = (w >> 1) * 32;

    float acc[4][4][4];
#pragma unroll
    for (int i = 0; i < 4; ++i)
#pragma unroll
        for (int j = 0; j < 4; ++j)
#pragma unroll
            for (int q = 0; q < 4; ++q) acc[i][j][q] = 0.0f;

    const int ns = K >> 5;

    const unsigned uA = (unsigned)__cvta_generic_to_shared(smem_dyn);
    const unsigned uB = uA + NSTAGE * STAGE_BYTES;

    const int atile   = l >> 3;
    const int arow0   = mw + (atile & 1) * 8 + (l & 7);
    const int achunk  = atile >> 1;
    const int bsel    = l >> 4;
    const int bchunk  = (l >> 3) & 1;
    const int brow0   = nw + (l & 7);

    auto load_stage = [&](int s, int buf) {
        int k0 = s << 5;
#pragma unroll
        for (int i = 0; i < 2; ++i) {
            int lin = i * 256 + t;
            int r = lin >> 2;
            int seg = lin & 3;
            int ar = bm + r;
            if (ar >= Nrows) ar = Nrows - 1;
            unsigned sa = uA + (unsigned)(buf * STAGE_BYTES + r * 80 + seg * 16);
            CP_ASYNC16(sa, &A[(size_t)ar * K + k0 + seg * 8]);
        }
#pragma unroll
        for (int i = 0; i < 2; ++i) {
            int lin = i * 256 + t;
            int r = lin >> 2;
            int seg = lin & 3;
            unsigned sa = uB + (unsigned)(buf * STAGE_BYTES + r * 80 + seg * 16);
            CP_ASYNC16(sa, &Wt[(size_t)(bn + r) * K + k0 + seg * 8]);
        }
    };

    int pre = ns < 3 ? ns : 3;
    for (int s = 0; s < pre; ++s) { load_stage(s, s); CP_COMMIT(); }

    for (int s = 0; s < ns; ++s) {
        CP_WAIT2();
        __syncthreads();

        if (s + 3 < ns) load_stage(s + 3, (s + 3) & (NSTAGE - 1));
        CP_COMMIT();

        const int buf = s & (NSTAGE - 1);
        const unsigned bufA = uA + (unsigned)(buf * STAGE_BYTES);
        const unsigned bufB = uB + (unsigned)(buf * STAGE_BYTES);

#pragma unroll
        for (int ks = 0; ks < 2; ++ks) {
            const int kc2 = ks * 2;
            unsigned bf[4][2];
#pragma unroll
            for (int p = 0; p < 2; ++p) {
                int nf = p * 2 + bsel;
                unsigned addr = bufB + (unsigned)((brow0 + nf * 8) * 80 + (kc2 + bchunk) * 16);
                ldsm4(bf[p * 2][0], bf[p * 2][1], bf[p * 2 + 1][0], bf[p * 2 + 1][1], addr);
            }
            unsigned af[4][4];
#pragma unroll
            for (int mf = 0; mf < 4; ++mf) {
                unsigned addr = bufA + (unsigned)((arow0 + mf * 16) * 80 + (kc2 + achunk) * 16);
                ldsm4(af[mf][0], af[mf][1], af[mf][2], af[mf][3], addr);
            }
#pragma unroll
            for (int mf = 0; mf < 4; ++mf)
#pragma unroll
                for (int nf = 0; nf < 4; ++nf)
                    mma_f16(acc[mf][nf], af[mf], bf[nf]);
        }
    }

#pragma unroll
    for (int mf = 0; mf < 4; ++mf)
#pragma unroll
        for (int nf = 0; nf < 4; ++nf) {
            int row = bm + mw + mf * 16 + g;
            int col = bn + nw + nf * 8 + 2 * tg;
            if (row < Nrows)
                *(__half2*)&C[(size_t)row * M + col] =
                    __floats2half2_rn(acc[mf][nf][0], acc[mf][nf][1]);
            if (row + 8 < Nrows)
                *(__half2*)&C[(size_t)(row + 8) * M + col] =
                    __floats2half2_rn(acc[mf][nf][2], acc[mf][nf][3]);
        }
}

// ---------------- attention coefficients (fp16 h) ----------------
__global__ void attn_kernel(const __half* __restrict__ h,
                            const float* __restrict__ a_s,
                            const float* __restrict__ a_d,
                            float* __restrict__ als, float* __restrict__ ald,
                            int Nn, int H) {
    int w = (blockIdx.x * blockDim.x + threadIdx.x) >> 5;
    int lane = threadIdx.x & 31;
    if (w >= Nn * H) return;
    int node = w / H;
    int head = w - node * H;
    const uint2* hp = (const uint2*)(h + ((size_t)node * H + head) * FDIM);
    const float4* sp = (const float4*)(a_s + head * FDIM);
    const float4* dp = (const float4*)(a_d + head * FDIM);
    uint2 raw = hp[lane];
    float2 fa = __half22float2(*(__half2*)&raw.x);
    float2 fb = __half22float2(*(__half2*)&raw.y);
    float4 sv = sp[lane], dv = dp[lane];
    float s = fa.x * sv.x + fa.y * sv.y + fb.x * sv.z + fb.y * sv.w;
    float d = fa.x * dv.x + fa.y * dv.y + fb.x * dv.z + fb.y * dv.w;
#pragma unroll
    for (int o = 16; o > 0; o >>= 1) {
        s += __shfl_xor_sync(0xffffffffu, s, o);
        d += __shfl_xor_sync(0xffffffffu, d, o);
    }
    if (lane == 0) { als[w] = s; ald[w] = d; }
}

// ================= per-head GAT aggregation (warp/node, 4-edge pipeline) =======
// All lanes load the same als scalar (HW broadcast) and compute exp redundantly;
// den is therefore exact per-lane with no shuffles. Each pass touches only the
// 51MB head slice of hbuf -> L2 resident; 12 independent loads in flight.
template<bool POOL>
__global__ void gat_agg_head_kernel(const int* __restrict__ rowptr, const int* __restrict__ csrc,
                                    const __half* __restrict__ hbuf,
                                    const float* __restrict__ als, const float* __restrict__ ald,
                                    const float* __restrict__ bias,
                                    const int* __restrict__ batch,
                                    void* __restrict__ outp, int Nn, int Htot, int head) {
    int w = (blockIdx.x * blockDim.x + threadIdx.x) >> 5;
    int lane = threadIdx.x & 31;
    if (w >= Nn) return;
    int beg = rowptr[w], end = rowptr[w + 1];
    const size_t hstride = (size_t)Htot * FDIM;
    const size_t hoff = (size_t)head * FDIM + lane * 4;

    float aldv = ald[(size_t)w * Htot + head];
    float den = 0.0f;
    float4 acc = make_float4(0, 0, 0, 0);

    int i = beg;
    for (; i + 4 <= end; i += 4) {
        int s0 = csrc[i], s1 = csrc[i + 1], s2 = csrc[i + 2], s3 = csrc[i + 3];
        uint2 r0 = *(const uint2*)(hbuf + (size_t)s0 * hstride + hoff);
        uint2 r1 = *(const uint2*)(hbuf + (size_t)s1 * hstride + hoff);
        uint2 r2 = *(const uint2*)(hbuf + (size_t)s2 * hstride + hoff);
        uint2 r3 = *(const uint2*)(hbuf + (size_t)s3 * hstride + hoff);
        float a0 = als[(size_t)s0 * Htot + head];
        float a1 = als[(size_t)s1 * Htot + head];
        float a2 = als[(size_t)s2 * Htot + head];
        float a3 = als[(size_t)s3 * Htot + head];
        float e0 = expf(lrelu(a0 + aldv));
        float e1 = expf(lrelu(a1 + aldv));
        float e2 = expf(lrelu(a2 + aldv));
        float e3 = expf(lrelu(a3 + aldv));
        float2 f0a = __half22float2(*(__half2*)&r0.x), f0b = __half22float2(*(__half2*)&r0.y);
        float2 f1a = __half22float2(*(__half2*)&r1.x), f1b = __half22float2(*(__half2*)&r1.y);
        float2 f2a = __half22float2(*(__half2*)&r2.x), f2b = __half22float2(*(__half2*)&r2.y);
        float2 f3a = __half22float2(*(__half2*)&r3.x), f3b = __half22float2(*(__half2*)&r3.y);
        acc.x = fmaf(e0, f0a.x, fmaf(e1, f1a.x, fmaf(e2, f2a.x, fmaf(e3, f3a.x, acc.x))));
        acc.y = fmaf(e0, f0a.y, fmaf(e1, f1a.y, fmaf(e2, f2a.y, fmaf(e3, f3a.y, acc.y))));
        acc.z = fmaf(e0, f0b.x, fmaf(e1, f1b.x, fmaf(e2, f2b.x, fmaf(e3, f3b.x, acc.z))));
        acc.w = fmaf(e0, f0b.y, fmaf(e1, f1b.y, fmaf(e2, f2b.y, fmaf(e3, f3b.y, acc.w))));
        den += (e0 + e1) + (e2 + e3);
    }
    for (; i < end; ++i) {
        int s0 = csrc[i];
        uint2 r0 = *(const uint2*)(hbuf + (size_t)s0 * hstride + hoff);
        float a0 = als[(size_t)s0 * Htot + head];
        float e0 = expf(lrelu(a0 + aldv));
        float2 fa = __half22float2(*(__half2*)&r0.x);
        float2 fb = __half22float2(*(__half2*)&r0.y);
        acc.x = fmaf(e0, fa.x, acc.x);
        acc.y = fmaf(e0, fa.y, acc.y);
        acc.z = fmaf(e0, fb.x, acc.z);
        acc.w = fmaf(e0, fb.y, acc.w);
        den += e0;
    }

    float r = 1.0f / (den + 1e-16f);
    float4 bv = *(const float4*)&bias[head * FDIM + lane * 4];
    if (POOL) {
        float* outf = (float*)outp;
        float4 v;
        v.x = lrelu(acc.x * r + bv.x);
        v.y = lrelu(acc.y * r + bv.y);
        v.z = lrelu(acc.z * r + bv.z);
        v.w = lrelu(acc.w * r + bv.w);
        float4* p = (float4*)(outf + (size_t)batch[w] * FDIM) + lane;
        asm volatile("red.global.add.v4.f32 [%0], {%1,%2,%3,%4};"
                     :: "l"(p), "f"(v.x), "f"(v.y), "f"(v.z), "f"(v.w) : "memory");
    } else {
        __half* op = (__half*)outp + (size_t)w * hstride + head * FDIM + lane * 4;
        __half2 p0 = __floats2half2_rn(lrelu(acc.x * r + bv.x), lrelu(acc.y * r + bv.y));
        __half2 p1 = __floats2half2_rn(lrelu(acc.z * r + bv.z), lrelu(acc.w * r + bv.w));
        *(uint2*)op = make_uint2(*(unsigned*)&p0, *(unsigned*)&p1);
    }
}

// ---------------- pooling epilogue ----------------
__global__ void count_kernel(const int* __restrict__ batch, int* __restrict__ cnt, int Nn) {
    int n = blockIdx.x * blockDim.x + threadIdx.x;
    if (n < Nn) atomicAdd(&cnt[batch[n]], 1);
}
__global__ void out_kernel(const float* __restrict__ pool, const int* __restrict__ cnt,
                           float* __restrict__ out, int G) {
    int i = blockIdx.x * blockDim.x + threadIdx.x;
    if (i >= G * FDIM) return;
    int g = i >> 7;
    float c = (float)max(cnt[g], 1);
    out[i] = pool[i] / c;
}

// ---------------- host orchestration ----------------
extern "C" void kernel_launch(void* const* d_in, const int* in_sizes, int n_in,
                              void* d_out, int out_size) {
    const float* x   = (const float*)d_in[0];
    const int*   ei  = (const int*)d_in[1];
    const int*   bat = (const int*)d_in[2];
    const float* W1  = (const float*)d_in[3];
    const float* a1s = (const float*)d_in[4];
    const float* a1d = (const float*)d_in[5];
    const float* b1  = (const float*)d_in[6];
    const float* W2  = (const float*)d_in[7];
    const float* a2s = (const float*)d_in[8];
    const float* a2d = (const float*)d_in[9];
    const float* b2  = (const float*)d_in[10];
    const float* W3  = (const float*)d_in[11];
    const float* a3s = (const float*)d_in[12];
    const float* a3d = (const float*)d_in[13];
    const float* b3  = (const float*)d_in[14];

    int Nn = in_sizes[0] / FDIM;     // 200000
    int E  = in_sizes[1] / 2;        // 1600000
    int Et = E + Nn;
    const int* srcs = ei;
    const int* dsts = ei + E;

    __half *hbuf, *feat, *xh, *wt;
    float *als, *ald, *pool;
    int *cnt, *deg, *rowptr, *woff, *bsum, *csrc;
    cudaGetSymbolAddress((void**)&hbuf,   g_h);
    cudaGetSymbolAddress((void**)&feat,   g_feat);
    cudaGetSymbolAddress((void**)&xh,     g_xh);
    cudaGetSymbolAddress((void**)&wt,     g_wt);
    cudaGetSymbolAddress((void**)&als,    g_als);
    cudaGetSymbolAddress((void**)&ald,    g_ald);
    cudaGetSymbolAddress((void**)&pool,   g_pool);
    cudaGetSymbolAddress((void**)&cnt,    g_cnt);
    cudaGetSymbolAddress((void**)&deg,    g_deg);
    cudaGetSymbolAddress((void**)&rowptr, g_rowptr);
    cudaGetSymbolAddress((void**)&woff,   g_woff);
    cudaGetSymbolAddress((void**)&bsum,   g_bsum);
    cudaGetSymbolAddress((void**)&csrc,   g_csrc);

    cudaFuncSetAttribute(gemm_fp16_kernel,
                         cudaFuncAttributeMaxDynamicSharedMemorySize, GEMM_SMEM);

    __half* wt1 = wt;                    // [384][128]
    __half* wt2 = wt + 384 * 384;        // [384][384]
    __half* wt3 = wt + 2 * 384 * 384;    // [128][384]

    const unsigned aggGrid = (unsigned)(((size_t)Nn * 32 + 255) / 256);
    const int nbm = (Nn + GBM - 1) / GBM;    // 1563

    // launch order keeps GEMM1 at stream index 3 (ncu -s 5 -c 1 window)
    zero_i<<<512, 256>>>(deg, (size_t)Nn);                            // 0
    cvt_x_kernel<<<2048, 256>>>(x, xh, (size_t)Nn * FDIM / 2);        // 1
    cvt_w_kernel<<<(128 * 384 + 255) / 256, 256>>>(W1, wt1, 128, 384);// 2
    {
        dim3 ggrid(384 / GBN, nbm);                                   // 3 <- profiled
        gemm_fp16_kernel<<<ggrid, 256, GEMM_SMEM>>>(xh, wt1, hbuf, Nn, 128, 384);
    }
    deg_kernel<<<(Et + 255) / 256, 256>>>(dsts, E, Nn, deg);          // 4
    scan1_kernel<<<SCAN_NB, SCAN_B>>>(deg, rowptr, bsum, Nn);         // 5
    scan2_kernel<<<1, 256>>>(bsum, SCAN_NB);                          // 6
    scan3_kernel<<<SCAN_NB, SCAN_B>>>(rowptr, woff, bsum, Nn, Et);    // 7
    scatter_kernel<<<(Et + 255) / 256, 256>>>(srcs, dsts, E, Nn, woff, csrc);
    cvt_w_kernel<<<(384 * 384 + 255) / 256, 256>>>(W2, wt2, 384, 384);
    cvt_w_kernel<<<(384 * 128 + 255) / 256, 256>>>(W3, wt3, 384, 128);
    {
        long long nwt = (long long)Nn * 3 * 32;
        attn_kernel<<<(unsigned)((nwt + 255) / 256), 256>>>(hbuf, a1s, a1d, als, ald, Nn, 3);
    }
    for (int h = 0; h < 3; ++h)
        gat_agg_head_kernel<false><<<aggGrid, 256>>>(rowptr, csrc, hbuf, als, ald, b1, bat, feat, Nn, 3, h);

    // ---- layer 2: 384 -> 3x128 ----
    {
        dim3 ggrid(384 / GBN, nbm);
        gemm_fp16_kernel<<<ggrid, 256, GEMM_SMEM>>>(feat, wt2, hbuf, Nn, 384, 384);
        long long nwt = (long long)Nn * 3 * 32;
        attn_kernel<<<(unsigned)((nwt + 255) / 256), 256>>>(hbuf, a2s, a2d, als, ald, Nn, 3);
    }
    for (int h = 0; h < 3; ++h)
        gat_agg_head_kernel<false><<<aggGrid, 256>>>(rowptr, csrc, hbuf, als, ald, b2, bat, feat, Nn, 3, h);

    // ---- layer 3: 384 -> 1x128 + fused pooling scatter ----
    zero_f<<<512, 256>>>(pool, (size_t)NG * FDIM);
    zero_i<<<32, 256>>>(cnt, (size_t)NG);
    {
        dim3 ggrid(128 / GBN, nbm);
        gemm_fp16_kernel<<<ggrid, 256, GEMM_SMEM>>>(feat, wt3, hbuf, Nn, 384, 128);
        long long nwt = (long long)Nn * 1 * 32;
        attn_kernel<<<(unsigned)((nwt + 255) / 256), 256>>>(hbuf, a3s, a3d, als, ald, Nn, 1);
    }
    gat_agg_head_kernel<true><<<aggGrid, 256>>>(rowptr, csrc, hbuf, als, ald, b3, bat, pool, Nn, 1, 0);

    // ---- output ----
    count_kernel<<<(Nn + 255) / 256, 256>>>(bat, cnt, Nn);
    out_kernel<<<(NG * FDIM + 255) / 256, 256>>>(pool, cnt, (float*)d_out, NG);
}

// round 15
// speedup vs baseline: 1.1695x; 1.1695x over previous
#include <cuda_runtime.h>
#include <cuda_fp16.h>
#include <cstdint>

// ---------------- problem constants ----------------
#define NN      200000
#define NE      1600000
#define NG      5000
#define FDIM    128
#define MAXH    3
#define MAXM    (MAXH*FDIM)   // 384
#define ETOT    (NE + NN)
#define SCAN_B  1024
#define SCAN_NB ((NN + SCAN_B - 1) / SCAN_B)   // 196

// ---------------- scratch ----------------
__device__ __half g_h   [(size_t)NN * MAXM];   // GEMM output features (fp16)
__device__ __half g_feat[(size_t)NN * MAXM];   // layer input features (fp16)
__device__ __half g_xh  [(size_t)NN * FDIM];   // fp16 copy of input x
__device__ __half g_wt  [3 * 384 * 384];       // transposed fp16 weights
__device__ float g_als [(size_t)NN * MAXH];
__device__ float g_ald [(size_t)NN * MAXH];
__device__ float g_pool[(size_t)NG * FDIM];
__device__ int   g_cnt [NG];
__device__ int   g_deg [NN];
__device__ int   g_rowptr[NN + 1];
__device__ int   g_woff[NN];
__device__ int   g_bsum[256];
__device__ int   g_csrc[ETOT];

// ---------------- helpers ----------------
__device__ __forceinline__ float lrelu(float v) { return v > 0.0f ? v : 0.2f * v; }

__device__ __forceinline__ void mma_f16(float* d, const unsigned* a, const unsigned* b) {
    asm volatile(
        "mma.sync.aligned.m16n8k16.row.col.f32.f16.f16.f32 "
        "{%0,%1,%2,%3}, {%4,%5,%6,%7}, {%8,%9}, {%0,%1,%2,%3};"
        : "+f"(d[0]), "+f"(d[1]), "+f"(d[2]), "+f"(d[3])
        : "r"(a[0]), "r"(a[1]), "r"(a[2]), "r"(a[3]), "r"(b[0]), "r"(b[1]));
}

__device__ __forceinline__ void ldsm4(unsigned& r0, unsigned& r1, unsigned& r2, unsigned& r3,
                                      unsigned addr) {
    asm volatile("ldmatrix.sync.aligned.m8n8.x4.shared.b16 {%0,%1,%2,%3}, [%4];"
                 : "=r"(r0), "=r"(r1), "=r"(r2), "=r"(r3) : "r"(addr));
}

#define CP_ASYNC16(saddr, gptr) \
    asm volatile("cp.async.cg.shared.global [%0], [%1], 16;" :: "r"(saddr), "l"(gptr))
#define CP_COMMIT() asm volatile("cp.async.commit_group;")
#define CP_WAIT2()  asm volatile("cp.async.wait_group 2;")

// ---------------- small utility kernels ----------------
__global__ void zero_f(float* p, size_t n) {
    size_t i = (size_t)blockIdx.x * blockDim.x + threadIdx.x;
    size_t stride = (size_t)gridDim.x * blockDim.x;
    for (; i < n; i += stride) p[i] = 0.0f;
}
__global__ void zero_i(int* p, size_t n) {
    size_t i = (size_t)blockIdx.x * blockDim.x + threadIdx.x;
    size_t stride = (size_t)gridDim.x * blockDim.x;
    for (; i < n; i += stride) p[i] = 0;
}
__global__ void cvt_x_kernel(const float* __restrict__ x, __half* __restrict__ xh, size_t n2) {
    size_t i = (size_t)blockIdx.x * blockDim.x + threadIdx.x;
    size_t stride = (size_t)gridDim.x * blockDim.x;
    for (; i < n2; i += stride) {
        float2 v = ((const float2*)x)[i];
        ((__half2*)xh)[i] = __floats2half2_rn(v.x, v.y);
    }
}
__global__ void cvt_w_kernel(const float* __restrict__ W, __half* __restrict__ Wt, int K, int M) {
    int idx = blockIdx.x * blockDim.x + threadIdx.x;
    if (idx >= K * M) return;
    int k = idx / M, m = idx - k * M;
    Wt[(size_t)m * K + k] = __float2half_rn(W[idx]);
}

// ================= CSR construction (by destination) =================
__global__ void deg_kernel(const int* __restrict__ dsts, int E, int Nn, int* __restrict__ deg) {
    int e = blockIdx.x * blockDim.x + threadIdx.x;
    int Et = E + Nn;
    if (e >= Et) return;
    int d = (e < E) ? dsts[e] : (e - E);
    atomicAdd(&deg[d], 1);
}

__global__ void scan1_kernel(const int* __restrict__ deg, int* __restrict__ excl,
                             int* __restrict__ bsum, int n) {
    __shared__ int sm[SCAN_B];
    int t = threadIdx.x;
    int gid = blockIdx.x * SCAN_B + t;
    int v = (gid < n) ? deg[gid] : 0;
    sm[t] = v;
    __syncthreads();
#pragma unroll
    for (int o = 1; o < SCAN_B; o <<= 1) {
        int u = (t >= o) ? sm[t - o] : 0;
        __syncthreads();
        sm[t] += u;
        __syncthreads();
    }
    if (gid < n) excl[gid] = sm[t] - v;
    if (t == SCAN_B - 1) bsum[blockIdx.x] = sm[t];
}

__global__ void scan2_kernel(int* __restrict__ bsum, int nb) {
    __shared__ int sm[256];
    int t = threadIdx.x;
    int v = (t < nb) ? bsum[t] : 0;
    sm[t] = v;
    __syncthreads();
#pragma unroll
    for (int o = 1; o < 256; o <<= 1) {
        int u = (t >= o) ? sm[t - o] : 0;
        __syncthreads();
        sm[t] += u;
        __syncthreads();
    }
    if (t < nb) bsum[t] = sm[t] - v;
}

__global__ void scan3_kernel(int* __restrict__ rowptr, int* __restrict__ woff,
                             const int* __restrict__ bsum, int n, int Et) {
    int gid = blockIdx.x * SCAN_B + threadIdx.x;
    if (gid < n) {
        int v = rowptr[gid] + bsum[gid >> 10];
        rowptr[gid] = v;
        woff[gid] = v;
    }
    if (gid == 0) rowptr[n] = Et;
}

__global__ void scatter_kernel(const int* __restrict__ srcs, const int* __restrict__ dsts,
                               int E, int Nn, int* __restrict__ woff, int* __restrict__ csrc) {
    int e = blockIdx.x * blockDim.x + threadIdx.x;
    int Et = E + Nn;
    if (e >= Et) return;
    int s, d;
    if (e < E) { s = srcs[e]; d = dsts[e]; }
    else       { s = d = e - E; }
    int pos = atomicAdd(&woff[d], 1);
    csrc[pos] = s;
}

// ================= tensor-core GEMM: fp16, 4-stage cp.async pipeline ===========
#define GBM 128
#define GBN 128
#define TST 20
#define STAGE_BYTES (GBM * TST * 4)   // 10240
#define NSTAGE 4
#define GEMM_SMEM (NSTAGE * STAGE_BYTES * 2)   // 81920

__global__ __launch_bounds__(256, 2) void gemm_fp16_kernel(const __half* __restrict__ A,
                                                           const __half* __restrict__ Wt,
                                                           __half* __restrict__ C,
                                                           int Nrows, int K, int M) {
    extern __shared__ unsigned smem_dyn[];

    const int bm = blockIdx.y * GBM;
    const int bn = blockIdx.x * GBN;
    const int t  = threadIdx.x;
    const int w  = t >> 5;
    const int l  = t & 31;
    const int g  = l >> 2;
    const int tg = l & 3;
    const int mw = (w & 1) * 64;
    const int nw = (w >> 1) * 32;

    float acc[4][4][4];
#pragma unroll
    for (int i = 0; i < 4; ++i)
#pragma unroll
        for (int j = 0; j < 4; ++j)
#pragma unroll
            for (int q = 0; q < 4; ++q) acc[i][j][q] = 0.0f;

    const int ns = K >> 5;

    const unsigned uA = (unsigned)__cvta_generic_to_shared(smem_dyn);
    const unsigned uB = uA + NSTAGE * STAGE_BYTES;

    const int atile   = l >> 3;
    const int arow0   = mw + (atile & 1) * 8 + (l & 7);
    const int achunk  = atile >> 1;
    const int bsel    = l >> 4;
    const int bchunk  = (l >> 3) & 1;
    const int brow0   = nw + (l & 7);

    auto load_stage = [&](int s, int buf) {
        int k0 = s << 5;
#pragma unroll
        for (int i = 0; i < 2; ++i) {
            int lin = i * 256 + t;
            int r = lin >> 2;
            int seg = lin & 3;
            int ar = bm + r;
            if (ar >= Nrows) ar = Nrows - 1;
            unsigned sa = uA + (unsigned)(buf * STAGE_BYTES + r * 80 + seg * 16);
            CP_ASYNC16(sa, &A[(size_t)ar * K + k0 + seg * 8]);
        }
#pragma unroll
        for (int i = 0; i < 2; ++i) {
            int lin = i * 256 + t;
            int r = lin >> 2;
            int seg = lin & 3;
            unsigned sa = uB + (unsigned)(buf * STAGE_BYTES + r * 80 + seg * 16);
            CP_ASYNC16(sa, &Wt[(size_t)(bn + r) * K + k0 + seg * 8]);
        }
    };

    int pre = ns < 3 ? ns : 3;
    for (int s = 0; s < pre; ++s) { load_stage(s, s); CP_COMMIT(); }

    for (int s = 0; s < ns; ++s) {
        CP_WAIT2();
        __syncthreads();

        if (s + 3 < ns) load_stage(s + 3, (s + 3) & (NSTAGE - 1));
        CP_COMMIT();

        const int buf = s & (NSTAGE - 1);
        const unsigned bufA = uA + (unsigned)(buf * STAGE_BYTES);
        const unsigned bufB = uB + (unsigned)(buf * STAGE_BYTES);

#pragma unroll
        for (int ks = 0; ks < 2; ++ks) {
            const int kc2 = ks * 2;
            unsigned bf[4][2];
#pragma unroll
            for (int p = 0; p < 2; ++p) {
                int nf = p * 2 + bsel;
                unsigned addr = bufB + (unsigned)((brow0 + nf * 8) * 80 + (kc2 + bchunk) * 16);
                ldsm4(bf[p * 2][0], bf[p * 2][1], bf[p * 2 + 1][0], bf[p * 2 + 1][1], addr);
            }
            unsigned af[4][4];
#pragma unroll
            for (int mf = 0; mf < 4; ++mf) {
                unsigned addr = bufA + (unsigned)((arow0 + mf * 16) * 80 + (kc2 + achunk) * 16);
                ldsm4(af[mf][0], af[mf][1], af[mf][2], af[mf][3], addr);
            }
#pragma unroll
            for (int mf = 0; mf < 4; ++mf)
#pragma unroll
                for (int nf = 0; nf < 4; ++nf)
                    mma_f16(acc[mf][nf], af[mf], bf[nf]);
        }
    }

#pragma unroll
    for (int mf = 0; mf < 4; ++mf)
#pragma unroll
        for (int nf = 0; nf < 4; ++nf) {
            int row = bm + mw + mf * 16 + g;
            int col = bn + nw + nf * 8 + 2 * tg;
            if (row < Nrows)
                *(__half2*)&C[(size_t)row * M + col] =
                    __floats2half2_rn(acc[mf][nf][0], acc[mf][nf][1]);
            if (row + 8 < Nrows)
                *(__half2*)&C[(size_t)(row + 8) * M + col] =
                    __floats2half2_rn(acc[mf][nf][2], acc[mf][nf][3]);
        }
}

// ---------------- attention coefficients (fp16 h) ----------------
__global__ void attn_kernel(const __half* __restrict__ h,
                            const float* __restrict__ a_s,
                            const float* __restrict__ a_d,
                            float* __restrict__ als, float* __restrict__ ald,
                            int Nn, int H) {
    int w = (blockIdx.x * blockDim.x + threadIdx.x) >> 5;
    int lane = threadIdx.x & 31;
    if (w >= Nn * H) return;
    int node = w / H;
    int head = w - node * H;
    const uint2* hp = (const uint2*)(h + ((size_t)node * H + head) * FDIM);
    const float4* sp = (const float4*)(a_s + head * FDIM);
    const float4* dp = (const float4*)(a_d + head * FDIM);
    uint2 raw = hp[lane];
    float2 fa = __half22float2(*(__half2*)&raw.x);
    float2 fb = __half22float2(*(__half2*)&raw.y);
    float4 sv = sp[lane], dv = dp[lane];
    float s = fa.x * sv.x + fa.y * sv.y + fb.x * sv.z + fb.y * sv.w;
    float d = fa.x * dv.x + fa.y * dv.y + fb.x * dv.z + fb.y * dv.w;
#pragma unroll
    for (int o = 16; o > 0; o >>= 1) {
        s += __shfl_xor_sync(0xffffffffu, s, o);
        d += __shfl_xor_sync(0xffffffffu, d, o);
    }
    if (lane == 0) { als[w] = s; ald[w] = d; }
}

// ========== fused GAT aggregation (warp/node, CSR, combined heads, 3-edge SWP) ====
template<int H, bool POOL>
__global__ void gat_agg_kernel(const int* __restrict__ rowptr, const int* __restrict__ csrc,
                               const __half* __restrict__ hbuf,
                               const float* __restrict__ als, const float* __restrict__ ald,
                               const float* __restrict__ bias,
                               const int* __restrict__ batch,
                               void* __restrict__ outp, int Nn) {
    int w = (blockIdx.x * blockDim.x + threadIdx.x) >> 5;
    int lane = threadIdx.x & 31;
    if (w >= Nn) return;
    int beg = rowptr[w], end = rowptr[w + 1];
    const int M = H * FDIM;

    float aldv = (lane < H) ? ald[(size_t)w * H + lane] : 0.0f;
    float den[H];
    float4 acc[H];
#pragma unroll
    for (int h = 0; h < H; ++h) { den[h] = 0.0f; acc[h] = make_float4(0, 0, 0, 0); }

    int i = beg;
    for (; i + 3 <= end; i += 3) {
        int s0 = csrc[i], s1 = csrc[i + 1], s2 = csrc[i + 2];
        const uint2* hp0 = (const uint2*)(hbuf + (size_t)s0 * M) + lane;
        const uint2* hp1 = (const uint2*)(hbuf + (size_t)s1 * M) + lane;
        const uint2* hp2 = (const uint2*)(hbuf + (size_t)s2 * M) + lane;
        uint2 r0[H], r1[H], r2[H];
#pragma unroll
        for (int h = 0; h < H; ++h) { r0[h] = hp0[h * 32]; r1[h] = hp1[h * 32]; r2[h] = hp2[h * 32]; }
        float as0 = (lane < H) ? als[(size_t)s0 * H + lane] : 0.0f;
        float as1 = (lane < H) ? als[(size_t)s1 * H + lane] : 0.0f;
        float as2 = (lane < H) ? als[(size_t)s2 * H + lane] : 0.0f;
        float e0 = expf(lrelu(as0 + aldv));
        float e1 = expf(lrelu(as1 + aldv));
        float e2 = expf(lrelu(as2 + aldv));
#pragma unroll
        for (int h = 0; h < H; ++h) {
            float ex0 = __shfl_sync(0xffffffffu, e0, h);
            float ex1 = __shfl_sync(0xffffffffu, e1, h);
            float ex2 = __shfl_sync(0xffffffffu, e2, h);
            float2 fa = __half22float2(*(__half2*)&r0[h].x);
            float2 fb = __half22float2(*(__half2*)&r0[h].y);
            float2 ga = __half22float2(*(__half2*)&r1[h].x);
            float2 gb = __half22float2(*(__half2*)&r1[h].y);
            float2 ha = __half22float2(*(__half2*)&r2[h].x);
            float2 hb = __half22float2(*(__half2*)&r2[h].y);
            acc[h].x = fmaf(ex0, fa.x, fmaf(ex1, ga.x, fmaf(ex2, ha.x, acc[h].x)));
            acc[h].y = fmaf(ex0, fa.y, fmaf(ex1, ga.y, fmaf(ex2, ha.y, acc[h].y)));
            acc[h].z = fmaf(ex0, fb.x, fmaf(ex1, gb.x, fmaf(ex2, hb.x, acc[h].z)));
            acc[h].w = fmaf(ex0, fb.y, fmaf(ex1, gb.y, fmaf(ex2, hb.y, acc[h].w)));
            den[h] += (ex0 + ex1) + ex2;
        }
    }
    for (; i < end; ++i) {
        int s0 = csrc[i];
        const uint2* hp0 = (const uint2*)(hbuf + (size_t)s0 * M) + lane;
        uint2 r0[H];
#pragma unroll
        for (int h = 0; h < H; ++h) r0[h] = hp0[h * 32];
        float as0 = (lane < H) ? als[(size_t)s0 * H + lane] : 0.0f;
        float e0 = expf(lrelu(as0 + aldv));
#pragma unroll
        for (int h = 0; h < H; ++h) {
            float ex0 = __shfl_sync(0xffffffffu, e0, h);
            float2 fa = __half22float2(*(__half2*)&r0[h].x);
            float2 fb = __half22float2(*(__half2*)&r0[h].y);
            acc[h].x = fmaf(ex0, fa.x, acc[h].x);
            acc[h].y = fmaf(ex0, fa.y, acc[h].y);
            acc[h].z = fmaf(ex0, fb.x, acc[h].z);
            acc[h].w = fmaf(ex0, fb.y, acc[h].w);
            den[h] += ex0;
        }
    }

    if (POOL) {
        float* outf = (float*)outp;
        float r = 1.0f / (den[0] + 1e-16f);
        float4 bv = *(const float4*)&bias[lane * 4];
        float4 v;
        v.x = lrelu(acc[0].x * r + bv.x);
        v.y = lrelu(acc[0].y * r + bv.y);
        v.z = lrelu(acc[0].z * r + bv.z);
        v.w = lrelu(acc[0].w * r + bv.w);
        float4* p = (float4*)(outf + (size_t)batch[w] * FDIM) + lane;
        asm volatile("red.global.add.v4.f32 [%0], {%1,%2,%3,%4};"
                     :: "l"(p), "f"(v.x), "f"(v.y), "f"(v.z), "f"(v.w) : "memory");
    } else {
        __half* op = (__half*)outp + (size_t)w * M;
#pragma unroll
        for (int h = 0; h < H; ++h) {
            float r = 1.0f / (den[h] + 1e-16f);
            float4 bv = *(const float4*)&bias[h * FDIM + lane * 4];
            __half2 p0 = __floats2half2_rn(lrelu(acc[h].x * r + bv.x),
                                           lrelu(acc[h].y * r + bv.y));
            __half2 p1 = __floats2half2_rn(lrelu(acc[h].z * r + bv.z),
                                           lrelu(acc[h].w * r + bv.w));
            *(uint2*)&op[h * FDIM + lane * 4] =
                make_uint2(*(unsigned*)&p0, *(unsigned*)&p1);
        }
    }
}

// ---------------- pooling epilogue ----------------
__global__ void count_kernel(const int* __restrict__ batch, int* __restrict__ cnt, int Nn) {
    int n = blockIdx.x * blockDim.x + threadIdx.x;
    if (n < Nn) atomicAdd(&cnt[batch[n]], 1);
}
__global__ void out_kernel(const float* __restrict__ pool, const int* __restrict__ cnt,
                           float* __restrict__ out, int G) {
    int i = blockIdx.x * blockDim.x + threadIdx.x;
    if (i >= G * FDIM) return;
    int g = i >> 7;
    float c = (float)max(cnt[g], 1);
    out[i] = pool[i] / c;
}

// ---------------- host orchestration ----------------
extern "C" void kernel_launch(void* const* d_in, const int* in_sizes, int n_in,
                              void* d_out, int out_size) {
    const float* x   = (const float*)d_in[0];
    const int*   ei  = (const int*)d_in[1];
    const int*   bat = (const int*)d_in[2];
    const float* W1  = (const float*)d_in[3];
    const float* a1s = (const float*)d_in[4];
    const float* a1d = (const float*)d_in[5];
    const float* b1  = (const float*)d_in[6];
    const float* W2  = (const float*)d_in[7];
    const float* a2s = (const float*)d_in[8];
    const float* a2d = (const float*)d_in[9];
    const float* b2  = (const float*)d_in[10];
    const float* W3  = (const float*)d_in[11];
    const float* a3s = (const float*)d_in[12];
    const float* a3d = (const float*)d_in[13];
    const float* b3  = (const float*)d_in[14];

    int Nn = in_sizes[0] / FDIM;     // 200000
    int E  = in_sizes[1] / 2;        // 1600000
    int Et = E + Nn;
    const int* srcs = ei;
    const int* dsts = ei + E;

    __half *hbuf, *feat, *xh, *wt;
    float *als, *ald, *pool;
    int *cnt, *deg, *rowptr, *woff, *bsum, *csrc;
    cudaGetSymbolAddress((void**)&hbuf,   g_h);
    cudaGetSymbolAddress((void**)&feat,   g_feat);
    cudaGetSymbolAddress((void**)&xh,     g_xh);
    cudaGetSymbolAddress((void**)&wt,     g_wt);
    cudaGetSymbolAddress((void**)&als,    g_als);
    cudaGetSymbolAddress((void**)&ald,    g_ald);
    cudaGetSymbolAddress((void**)&pool,   g_pool);
    cudaGetSymbolAddress((void**)&cnt,    g_cnt);
    cudaGetSymbolAddress((void**)&deg,    g_deg);
    cudaGetSymbolAddress((void**)&rowptr, g_rowptr);
    cudaGetSymbolAddress((void**)&woff,   g_woff);
    cudaGetSymbolAddress((void**)&bsum,   g_bsum);
    cudaGetSymbolAddress((void**)&csrc,   g_csrc);

    cudaFuncSetAttribute(gemm_fp16_kernel,
                         cudaFuncAttributeMaxDynamicSharedMemorySize, GEMM_SMEM);

    __half* wt1 = wt;                    // [384][128]
    __half* wt2 = wt + 384 * 384;        // [384][384]
    __half* wt3 = wt + 2 * 384 * 384;    // [128][384]

    const unsigned aggGrid = (unsigned)(((size_t)Nn * 32 + 255) / 256);
    const int nbm = (Nn + GBM - 1) / GBM;    // 1563

    // launch order keeps GEMM1 at stream index 3 (ncu -s 5 -c 1 window)
    zero_i<<<512, 256>>>(deg, (size_t)Nn);                            // 0
    cvt_x_kernel<<<2048, 256>>>(x, xh, (size_t)Nn * FDIM / 2);        // 1
    cvt_w_kernel<<<(128 * 384 + 255) / 256, 256>>>(W1, wt1, 128, 384);// 2
    {
        dim3 ggrid(384 / GBN, nbm);                                   // 3 <- profiled
        gemm_fp16_kernel<<<ggrid, 256, GEMM_SMEM>>>(xh, wt1, hbuf, Nn, 128, 384);
    }
    deg_kernel<<<(Et + 255) / 256, 256>>>(dsts, E, Nn, deg);          // 4
    scan1_kernel<<<SCAN_NB, SCAN_B>>>(deg, rowptr, bsum, Nn);         // 5
    scan2_kernel<<<1, 256>>>(bsum, SCAN_NB);                          // 6
    scan3_kernel<<<SCAN_NB, SCAN_B>>>(rowptr, woff, bsum, Nn, Et);    // 7
    scatter_kernel<<<(Et + 255) / 256, 256>>>(srcs, dsts, E, Nn, woff, csrc);
    cvt_w_kernel<<<(384 * 384 + 255) / 256, 256>>>(W2, wt2, 384, 384);
    cvt_w_kernel<<<(384 * 128 + 255) / 256, 256>>>(W3, wt3, 384, 128);
    {
        long long nwt = (long long)Nn * 3 * 32;
        attn_kernel<<<(unsigned)((nwt + 255) / 256), 256>>>(hbuf, a1s, a1d, als, ald, Nn, 3);
    }
    gat_agg_kernel<3, false><<<aggGrid, 256>>>(rowptr, csrc, hbuf, als, ald, b1, bat, feat, Nn);

    // ---- layer 2: 384 -> 3x128 ----
    {
        dim3 ggrid(384 / GBN, nbm);
        gemm_fp16_kernel<<<ggrid, 256, GEMM_SMEM>>>(feat, wt2, hbuf, Nn, 384, 384);
        long long nwt = (long long)Nn * 3 * 32;
        attn_kernel<<<(unsigned)((nwt + 255) / 256), 256>>>(hbuf, a2s, a2d, als, ald, Nn, 3);
    }
    gat_agg_kernel<3, false><<<aggGrid, 256>>>(rowptr, csrc, hbuf, als, ald, b2, bat, feat, Nn);

    // ---- layer 3: 384 -> 1x128 + fused pooling scatter ----
    zero_f<<<512, 256>>>(pool, (size_t)NG * FDIM);
    zero_i<<<32, 256>>>(cnt, (size_t)NG);
    {
        dim3 ggrid(128 / GBN, nbm);
        gemm_fp16_kernel<<<ggrid, 256, GEMM_SMEM>>>(feat, wt3, hbuf, Nn, 384, 128);
        long long nwt = (long long)Nn * 1 * 32;
        attn_kernel<<<(unsigned)((nwt + 255) / 256), 256>>>(hbuf, a3s, a3d, als, ald, Nn, 1);
    }
    gat_agg_kernel<1, true><<<aggGrid, 256>>>(rowptr, csrc, hbuf, als, ald, b3, bat, pool, Nn);

    // ---- output ----
    count_kernel<<<(Nn + 255) / 256, 256>>>(bat, cnt, Nn);
    out_kernel<<<(NG * FDIM + 255) / 256, 256>>>(pool, cnt, (float*)d_out, NG);
}

// round 16
// speedup vs baseline: 1.2266x; 1.0489x over previous
#include <cuda_runtime.h>
#include <cuda_fp16.h>
#include <cstdint>

// ---------------- problem constants ----------------
#define NN      200000
#define NE      1600000
#define NG      5000
#define FDIM    128
#define MAXH    3
#define MAXM    (MAXH*FDIM)   // 384
#define ETOT    (NE + NN)
#define SCAN_B  1024
#define SCAN_NB ((NN + SCAN_B - 1) / SCAN_B)   // 196

// ---------------- scratch ----------------
__device__ __half g_h   [(size_t)NN * MAXM];   // GEMM output features (fp16)
__device__ __half g_feat[(size_t)NN * MAXM];   // layer input features (fp16)
__device__ __half g_xh  [(size_t)NN * FDIM];   // fp16 copy of input x
__device__ __half g_wt  [3 * 384 * 384];       // transposed fp16 weights
__device__ float g_als [(size_t)NN * MAXH];
__device__ float g_ald [(size_t)NN * MAXH];
__device__ float g_pool[(size_t)NG * FDIM];
__device__ int   g_cnt [NG];
__device__ int   g_deg [NN];
__device__ int   g_rowptr[NN + 1];
__device__ int   g_woff[NN];
__device__ int   g_bsum[256];
__device__ int   g_csrc[ETOT];

// ---------------- helpers ----------------
__device__ __forceinline__ float lrelu(float v) { return v > 0.0f ? v : 0.2f * v; }

__device__ __forceinline__ void mma_f16(float* d, const unsigned* a, const unsigned* b) {
    asm volatile(
        "mma.sync.aligned.m16n8k16.row.col.f32.f16.f16.f32 "
        "{%0,%1,%2,%3}, {%4,%5,%6,%7}, {%8,%9}, {%0,%1,%2,%3};"
        : "+f"(d[0]), "+f"(d[1]), "+f"(d[2]), "+f"(d[3])
        : "r"(a[0]), "r"(a[1]), "r"(a[2]), "r"(a[3]), "r"(b[0]), "r"(b[1]));
}

__device__ __forceinline__ void ldsm4(unsigned& r0, unsigned& r1, unsigned& r2, unsigned& r3,
                                      unsigned addr) {
    asm volatile("ldmatrix.sync.aligned.m8n8.x4.shared.b16 {%0,%1,%2,%3}, [%4];"
                 : "=r"(r0), "=r"(r1), "=r"(r2), "=r"(r3) : "r"(addr));
}

#define CP_ASYNC16(saddr, gptr) \
    asm volatile("cp.async.cg.shared.global [%0], [%1], 16;" :: "r"(saddr), "l"(gptr))
#define CP_COMMIT() asm volatile("cp.async.commit_group;")
#define CP_WAIT2()  asm volatile("cp.async.wait_group 2;")

// ---------------- small utility kernels ----------------
__global__ void zero_f(float* p, size_t n) {
    size_t i = (size_t)blockIdx.x * blockDim.x + threadIdx.x;
    size_t stride = (size_t)gridDim.x * blockDim.x;
    for (; i < n; i += stride) p[i] = 0.0f;
}
__global__ void zero_i(int* p, size_t n) {
    size_t i = (size_t)blockIdx.x * blockDim.x + threadIdx.x;
    size_t stride = (size_t)gridDim.x * blockDim.x;
    for (; i < n; i += stride) p[i] = 0;
}
__global__ void cvt_x_kernel(const float* __restrict__ x, __half* __restrict__ xh, size_t n2) {
    size_t i = (size_t)blockIdx.x * blockDim.x + threadIdx.x;
    size_t stride = (size_t)gridDim.x * blockDim.x;
    for (; i < n2; i += stride) {
        float2 v = ((const float2*)x)[i];
        ((__half2*)xh)[i] = __floats2half2_rn(v.x, v.y);
    }
}
__global__ void cvt_w_kernel(const float* __restrict__ W, __half* __restrict__ Wt, int K, int M) {
    int idx = blockIdx.x * blockDim.x + threadIdx.x;
    if (idx >= K * M) return;
    int k = idx / M, m = idx - k * M;
    Wt[(size_t)m * K + k] = __float2half_rn(W[idx]);
}

// ================= CSR construction (by destination) =================
__global__ void deg_kernel(const int* __restrict__ dsts, int E, int Nn, int* __restrict__ deg) {
    int e = blockIdx.x * blockDim.x + threadIdx.x;
    int Et = E + Nn;
    if (e >= Et) return;
    int d = (e < E) ? dsts[e] : (e - E);
    atomicAdd(&deg[d], 1);
}

__global__ void scan1_kernel(const int* __restrict__ deg, int* __restrict__ excl,
                             int* __restrict__ bsum, int n) {
    __shared__ int sm[SCAN_B];
    int t = threadIdx.x;
    int gid = blockIdx.x * SCAN_B + t;
    int v = (gid < n) ? deg[gid] : 0;
    sm[t] = v;
    __syncthreads();
#pragma unroll
    for (int o = 1; o < SCAN_B; o <<= 1) {
        int u = (t >= o) ? sm[t - o] : 0;
        __syncthreads();
        sm[t] += u;
        __syncthreads();
    }
    if (gid < n) excl[gid] = sm[t] - v;
    if (t == SCAN_B - 1) bsum[blockIdx.x] = sm[t];
}

__global__ void scan2_kernel(int* __restrict__ bsum, int nb) {
    __shared__ int sm[256];
    int t = threadIdx.x;
    int v = (t < nb) ? bsum[t] : 0;
    sm[t] = v;
    __syncthreads();
#pragma unroll
    for (int o = 1; o < 256; o <<= 1) {
        int u = (t >= o) ? sm[t - o] : 0;
        __syncthreads();
        sm[t] += u;
        __syncthreads();
    }
    if (t < nb) bsum[t] = sm[t] - v;
}

__global__ void scan3_kernel(int* __restrict__ rowptr, int* __restrict__ woff,
                             const int* __restrict__ bsum, int n, int Et) {
    int gid = blockIdx.x * SCAN_B + threadIdx.x;
    if (gid < n) {
        int v = rowptr[gid] + bsum[gid >> 10];
        rowptr[gid] = v;
        woff[gid] = v;
    }
    if (gid == 0) rowptr[n] = Et;
}

__global__ void scatter_kernel(const int* __restrict__ srcs, const int* __restrict__ dsts,
                               int E, int Nn, int* __restrict__ woff, int* __restrict__ csrc) {
    int e = blockIdx.x * blockDim.x + threadIdx.x;
    int Et = E + Nn;
    if (e >= Et) return;
    int s, d;
    if (e < E) { s = srcs[e]; d = dsts[e]; }
    else       { s = d = e - E; }
    int pos = atomicAdd(&woff[d], 1);
    csrc[pos] = s;
}

// ================= tensor-core GEMM: fp16, 4-stage cp.async pipeline ===========
#define GBM 128
#define GBN 128
#define TST 20
#define STAGE_BYTES (GBM * TST * 4)   // 10240
#define NSTAGE 4
#define GEMM_SMEM (NSTAGE * STAGE_BYTES * 2)   // 81920

__global__ __launch_bounds__(256, 2) void gemm_fp16_kernel(const __half* __restrict__ A,
                                                           const __half* __restrict__ Wt,
                                                           __half* __restrict__ C,
                                                           int Nrows, int K, int M) {
    extern __shared__ unsigned smem_dyn[];

    const int bm = blockIdx.y * GBM;
    const int bn = blockIdx.x * GBN;
    const int t  = threadIdx.x;
    const int w  = t >> 5;
    const int l  = t & 31;
    const int g  = l >> 2;
    const int tg = l & 3;
    const int mw = (w & 1) * 64;
    const int nw = (w >> 1) * 32;

    float acc[4][4][4];
#pragma unroll
    for (int i = 0; i < 4; ++i)
#pragma unroll
        for (int j = 0; j < 4; ++j)
#pragma unroll
            for (int q = 0; q < 4; ++q) acc[i][j][q] = 0.0f;

    const int ns = K >> 5;

    const unsigned uA = (unsigned)__cvta_generic_to_shared(smem_dyn);
    const unsigned uB = uA + NSTAGE * STAGE_BYTES;

    const int atile   = l >> 3;
    const int arow0   = mw + (atile & 1) * 8 + (l & 7);
    const int achunk  = atile >> 1;
    const int bsel    = l >> 4;
    const int bchunk  = (l >> 3) & 1;
    const int brow0   = nw + (l & 7);

    auto load_stage = [&](int s, int buf) {
        int k0 = s << 5;
#pragma unroll
        for (int i = 0; i < 2; ++i) {
            int lin = i * 256 + t;
            int r = lin >> 2;
            int seg = lin & 3;
            int ar = bm + r;
            if (ar >= Nrows) ar = Nrows - 1;
            unsigned sa = uA + (unsigned)(buf * STAGE_BYTES + r * 80 + seg * 16);
            CP_ASYNC16(sa, &A[(size_t)ar * K + k0 + seg * 8]);
        }
#pragma unroll
        for (int i = 0; i < 2; ++i) {
            int lin = i * 256 + t;
            int r = lin >> 2;
            int seg = lin & 3;
            unsigned sa = uB + (unsigned)(buf * STAGE_BYTES + r * 80 + seg * 16);
            CP_ASYNC16(sa, &Wt[(size_t)(bn + r) * K + k0 + seg * 8]);
        }
    };

    int pre = ns < 3 ? ns : 3;
    for (int s = 0; s < pre; ++s) { load_stage(s, s); CP_COMMIT(); }

    for (int s = 0; s < ns; ++s) {
        CP_WAIT2();
        __syncthreads();

        if (s + 3 < ns) load_stage(s + 3, (s + 3) & (NSTAGE - 1));
        CP_COMMIT();

        const int buf = s & (NSTAGE - 1);
        const unsigned bufA = uA + (unsigned)(buf * STAGE_BYTES);
        const unsigned bufB = uB + (unsigned)(buf * STAGE_BYTES);

#pragma unroll
        for (int ks = 0; ks < 2; ++ks) {
            const int kc2 = ks * 2;
            unsigned bf[4][2];
#pragma unroll
            for (int p = 0; p < 2; ++p) {
                int nf = p * 2 + bsel;
                unsigned addr = bufB + (unsigned)((brow0 + nf * 8) * 80 + (kc2 + bchunk) * 16);
                ldsm4(bf[p * 2][0], bf[p * 2][1], bf[p * 2 + 1][0], bf[p * 2 + 1][1], addr);
            }
            unsigned af[4][4];
#pragma unroll
            for (int mf = 0; mf < 4; ++mf) {
                unsigned addr = bufA + (unsigned)((arow0 + mf * 16) * 80 + (kc2 + achunk) * 16);
                ldsm4(af[mf][0], af[mf][1], af[mf][2], af[mf][3], addr);
            }
#pragma unroll
            for (int mf = 0; mf < 4; ++mf)
#pragma unroll
                for (int nf = 0; nf < 4; ++nf)
                    mma_f16(acc[mf][nf], af[mf], bf[nf]);
        }
    }

#pragma unroll
    for (int mf = 0; mf < 4; ++mf)
#pragma unroll
        for (int nf = 0; nf < 4; ++nf) {
            int row = bm + mw + mf * 16 + g;
            int col = bn + nw + nf * 8 + 2 * tg;
            if (row < Nrows)
                *(__half2*)&C[(size_t)row * M + col] =
                    __floats2half2_rn(acc[mf][nf][0], acc[mf][nf][1]);
            if (row + 8 < Nrows)
                *(__half2*)&C[(size_t)(row + 8) * M + col] =
                    __floats2half2_rn(acc[mf][nf][2], acc[mf][nf][3]);
        }
}

// ---------------- attention coefficients (fp16 h) ----------------
__global__ void attn_kernel(const __half* __restrict__ h,
                            const float* __restrict__ a_s,
                            const float* __restrict__ a_d,
                            float* __restrict__ als, float* __restrict__ ald,
                            int Nn, int H) {
    int w = (blockIdx.x * blockDim.x + threadIdx.x) >> 5;
    int lane = threadIdx.x & 31;
    if (w >= Nn * H) return;
    int node = w / H;
    int head = w - node * H;
    const uint2* hp = (const uint2*)(h + ((size_t)node * H + head) * FDIM);
    const float4* sp = (const float4*)(a_s + head * FDIM);
    const float4* dp = (const float4*)(a_d + head * FDIM);
    uint2 raw = hp[lane];
    float2 fa = __half22float2(*(__half2*)&raw.x);
    float2 fb = __half22float2(*(__half2*)&raw.y);
    float4 sv = sp[lane], dv = dp[lane];
    float s = fa.x * sv.x + fa.y * sv.y + fb.x * sv.z + fb.y * sv.w;
    float d = fa.x * dv.x + fa.y * dv.y + fb.x * dv.z + fb.y * dv.w;
#pragma unroll
    for (int o = 16; o > 0; o >>= 1) {
        s += __shfl_xor_sync(0xffffffffu, s, o);
        d += __shfl_xor_sync(0xffffffffu, d, o);
    }
    if (lane == 0) { als[w] = s; ald[w] = d; }
}

// ========== fused GAT aggregation (warp/node, CSR, combined heads, 2-edge SWP) ====
template<int H, bool POOL>
__global__ void gat_agg_kernel(const int* __restrict__ rowptr, const int* __restrict__ csrc,
                               const __half* __restrict__ hbuf,
                               const float* __restrict__ als, const float* __restrict__ ald,
                               const float* __restrict__ bias,
                               const int* __restrict__ batch,
                               void* __restrict__ outp, int Nn) {
    int w = (blockIdx.x * blockDim.x + threadIdx.x) >> 5;
    int lane = threadIdx.x & 31;
    if (w >= Nn) return;
    int beg = rowptr[w], end = rowptr[w + 1];
    const int M = H * FDIM;

    float aldv = (lane < H) ? ald[(size_t)w * H + lane] : 0.0f;
    float den[H];
    float4 acc[H];
#pragma unroll
    for (int h = 0; h < H; ++h) { den[h] = 0.0f; acc[h] = make_float4(0, 0, 0, 0); }

    int i = beg;
    for (; i + 2 <= end; i += 2) {
        int s0 = csrc[i], s1 = csrc[i + 1];
        const uint2* hp0 = (const uint2*)(hbuf + (size_t)s0 * M) + lane;
        const uint2* hp1 = (const uint2*)(hbuf + (size_t)s1 * M) + lane;
        uint2 r0[H], r1[H];
#pragma unroll
        for (int h = 0; h < H; ++h) { r0[h] = hp0[h * 32]; r1[h] = hp1[h * 32]; }
        float as0 = (lane < H) ? als[(size_t)s0 * H + lane] : 0.0f;
        float as1 = (lane < H) ? als[(size_t)s1 * H + lane] : 0.0f;
        float e0 = expf(lrelu(as0 + aldv));
        float e1 = expf(lrelu(as1 + aldv));
#pragma unroll
        for (int h = 0; h < H; ++h) {
            float ex0 = __shfl_sync(0xffffffffu, e0, h);
            float ex1 = __shfl_sync(0xffffffffu, e1, h);
            float2 fa = __half22float2(*(__half2*)&r0[h].x);
            float2 fb = __half22float2(*(__half2*)&r0[h].y);
            float2 ga = __half22float2(*(__half2*)&r1[h].x);
            float2 gb = __half22float2(*(__half2*)&r1[h].y);
            acc[h].x = fmaf(ex0, fa.x, fmaf(ex1, ga.x, acc[h].x));
            acc[h].y = fmaf(ex0, fa.y, fmaf(ex1, ga.y, acc[h].y));
            acc[h].z = fmaf(ex0, fb.x, fmaf(ex1, gb.x, acc[h].z));
            acc[h].w = fmaf(ex0, fb.y, fmaf(ex1, gb.y, acc[h].w));
            den[h] += ex0 + ex1;
        }
    }
    if (i < end) {
        int s0 = csrc[i];
        const uint2* hp0 = (const uint2*)(hbuf + (size_t)s0 * M) + lane;
        uint2 r0[H];
#pragma unroll
        for (int h = 0; h < H; ++h) r0[h] = hp0[h * 32];
        float as0 = (lane < H) ? als[(size_t)s0 * H + lane] : 0.0f;
        float e0 = expf(lrelu(as0 + aldv));
#pragma unroll
        for (int h = 0; h < H; ++h) {
            float ex0 = __shfl_sync(0xffffffffu, e0, h);
            float2 fa = __half22float2(*(__half2*)&r0[h].x);
            float2 fb = __half22float2(*(__half2*)&r0[h].y);
            acc[h].x = fmaf(ex0, fa.x, acc[h].x);
            acc[h].y = fmaf(ex0, fa.y, acc[h].y);
            acc[h].z = fmaf(ex0, fb.x, acc[h].z);
            acc[h].w = fmaf(ex0, fb.y, acc[h].w);
            den[h] += ex0;
        }
    }

    if (POOL) {
        float* outf = (float*)outp;
        float r = 1.0f / (den[0] + 1e-16f);
        float4 bv = *(const float4*)&bias[lane * 4];
        float4 v;
        v.x = lrelu(acc[0].x * r + bv.x);
        v.y = lrelu(acc[0].y * r + bv.y);
        v.z = lrelu(acc[0].z * r + bv.z);
        v.w = lrelu(acc[0].w * r + bv.w);
        float4* p = (float4*)(outf + (size_t)batch[w] * FDIM) + lane;
        asm volatile("red.global.add.v4.f32 [%0], {%1,%2,%3,%4};"
                     :: "l"(p), "f"(v.x), "f"(v.y), "f"(v.z), "f"(v.w) : "memory");
    } else {
        __half* op = (__half*)outp + (size_t)w * M;
#pragma unroll
        for (int h = 0; h < H; ++h) {
            float r = 1.0f / (den[h] + 1e-16f);
            float4 bv = *(const float4*)&bias[h * FDIM + lane * 4];
            __half2 p0 = __floats2half2_rn(lrelu(acc[h].x * r + bv.x),
                                           lrelu(acc[h].y * r + bv.y));
            __half2 p1 = __floats2half2_rn(lrelu(acc[h].z * r + bv.z),
                                           lrelu(acc[h].w * r + bv.w));
            *(uint2*)&op[h * FDIM + lane * 4] =
                make_uint2(*(unsigned*)&p0, *(unsigned*)&p1);
        }
    }
}

// ---------------- pooling epilogue ----------------
__global__ void count_kernel(const int* __restrict__ batch, int* __restrict__ cnt, int Nn) {
    int n = blockIdx.x * blockDim.x + threadIdx.x;
    if (n < Nn) atomicAdd(&cnt[batch[n]], 1);
}
__global__ void out_kernel(const float* __restrict__ pool, const int* __restrict__ cnt,
                           float* __restrict__ out, int G) {
    int i = blockIdx.x * blockDim.x + threadIdx.x;
    if (i >= G * FDIM) return;
    int g = i >> 7;
    float c = (float)max(cnt[g], 1);
    out[i] = pool[i] / c;
}

// ---------------- host orchestration ----------------
extern "C" void kernel_launch(void* const* d_in, const int* in_sizes, int n_in,
                              void* d_out, int out_size) {
    const float* x   = (const float*)d_in[0];
    const int*   ei  = (const int*)d_in[1];
    const int*   bat = (const int*)d_in[2];
    const float* W1  = (const float*)d_in[3];
    const float* a1s = (const float*)d_in[4];
    const float* a1d = (const float*)d_in[5];
    const float* b1  = (const float*)d_in[6];
    const float* W2  = (const float*)d_in[7];
    const float* a2s = (const float*)d_in[8];
    const float* a2d = (const float*)d_in[9];
    const float* b2  = (const float*)d_in[10];
    const float* W3  = (const float*)d_in[11];
    const float* a3s = (const float*)d_in[12];
    const float* a3d = (const float*)d_in[13];
    const float* b3  = (const float*)d_in[14];

    int Nn = in_sizes[0] / FDIM;     // 200000
    int E  = in_sizes[1] / 2;        // 1600000
    int Et = E + Nn;
    const int* srcs = ei;
    const int* dsts = ei + E;

    __half *hbuf, *feat, *xh, *wt;
    float *als, *ald, *pool;
    int *cnt, *deg, *rowptr, *woff, *bsum, *csrc;
    cudaGetSymbolAddress((void**)&hbuf,   g_h);
    cudaGetSymbolAddress((void**)&feat,   g_feat);
    cudaGetSymbolAddress((void**)&xh,     g_xh);
    cudaGetSymbolAddress((void**)&wt,     g_wt);
    cudaGetSymbolAddress((void**)&als,    g_als);
    cudaGetSymbolAddress((void**)&ald,    g_ald);
    cudaGetSymbolAddress((void**)&pool,   g_pool);
    cudaGetSymbolAddress((void**)&cnt,    g_cnt);
    cudaGetSymbolAddress((void**)&deg,    g_deg);
    cudaGetSymbolAddress((void**)&rowptr, g_rowptr);
    cudaGetSymbolAddress((void**)&woff,   g_woff);
    cudaGetSymbolAddress((void**)&bsum,   g_bsum);
    cudaGetSymbolAddress((void**)&csrc,   g_csrc);

    cudaFuncSetAttribute(gemm_fp16_kernel,
                         cudaFuncAttributeMaxDynamicSharedMemorySize, GEMM_SMEM);

    __half* wt1 = wt;                    // [384][128]
    __half* wt2 = wt + 384 * 384;        // [384][384]
    __half* wt3 = wt + 2 * 384 * 384;    // [128][384]

    const unsigned aggGrid = (unsigned)(((size_t)Nn * 32 + 255) / 256);
    const int nbm = (Nn + GBM - 1) / GBM;    // 1563

    // ---- side stream for independent prework (fork/join is capture-legal) ----
    cudaStream_t s2;
    cudaStreamCreateWithFlags(&s2, cudaStreamNonBlocking);
    cudaEvent_t eFork, eJoin;
    cudaEventCreateWithFlags(&eFork, cudaEventDisableTiming);
    cudaEventCreateWithFlags(&eJoin, cudaEventDisableTiming);

    cudaEventRecord(eFork, 0);
    cudaStreamWaitEvent(s2, eFork, 0);

    // ---- side stream: CSR build + non-critical converts + pool prep ----
    zero_i<<<512, 256, 0, s2>>>(deg, (size_t)Nn);
    deg_kernel<<<(Et + 255) / 256, 256, 0, s2>>>(dsts, E, Nn, deg);
    scan1_kernel<<<SCAN_NB, SCAN_B, 0, s2>>>(deg, rowptr, bsum, Nn);
    scan2_kernel<<<1, 256, 0, s2>>>(bsum, SCAN_NB);
    scan3_kernel<<<SCAN_NB, SCAN_B, 0, s2>>>(rowptr, woff, bsum, Nn, Et);
    scatter_kernel<<<(Et + 255) / 256, 256, 0, s2>>>(srcs, dsts, E, Nn, woff, csrc);
    cvt_w_kernel<<<(384 * 384 + 255) / 256, 256, 0, s2>>>(W2, wt2, 384, 384);
    cvt_w_kernel<<<(384 * 128 + 255) / 256, 256, 0, s2>>>(W3, wt3, 384, 128);
    zero_f<<<512, 256, 0, s2>>>(pool, (size_t)NG * FDIM);
    zero_i<<<32, 256, 0, s2>>>(cnt, (size_t)NG);
    count_kernel<<<(Nn + 255) / 256, 256, 0, s2>>>(bat, cnt, Nn);
    cudaEventRecord(eJoin, s2);

    // ---- main stream: layer-1 critical path ----
    cvt_x_kernel<<<2048, 256>>>(x, xh, (size_t)Nn * FDIM / 2);
    cvt_w_kernel<<<(128 * 384 + 255) / 256, 256>>>(W1, wt1, 128, 384);
    {
        dim3 ggrid(384 / GBN, nbm);                                   // <- profiled window
        gemm_fp16_kernel<<<ggrid, 256, GEMM_SMEM>>>(xh, wt1, hbuf, Nn, 128, 384);
    }
    {
        long long nwt = (long long)Nn * 3 * 32;
        attn_kernel<<<(unsigned)((nwt + 255) / 256), 256>>>(hbuf, a1s, a1d, als, ald, Nn, 3);
    }
    cudaStreamWaitEvent(0, eJoin, 0);   // join: agg needs rowptr/csrc; gemm2 needs wt2
    gat_agg_kernel<3, false><<<aggGrid, 256>>>(rowptr, csrc, hbuf, als, ald, b1, bat, feat, Nn);

    // ---- layer 2: 384 -> 3x128 ----
    {
        dim3 ggrid(384 / GBN, nbm);
        gemm_fp16_kernel<<<ggrid, 256, GEMM_SMEM>>>(feat, wt2, hbuf, Nn, 384, 384);
        long long nwt = (long long)Nn * 3 * 32;
        attn_kernel<<<(unsigned)((nwt + 255) / 256), 256>>>(hbuf, a2s, a2d, als, ald, Nn, 3);
    }
    gat_agg_kernel<3, false><<<aggGrid, 256>>>(rowptr, csrc, hbuf, als, ald, b2, bat, feat, Nn);

    // ---- layer 3: 384 -> 1x128 + fused pooling scatter ----
    {
        dim3 ggrid(128 / GBN, nbm);
        gemm_fp16_kernel<<<ggrid, 256, GEMM_SMEM>>>(feat, wt3, hbuf, Nn, 384, 128);
        long long nwt = (long long)Nn * 1 * 32;
        attn_kernel<<<(unsigned)((nwt + 255) / 256), 256>>>(hbuf, a3s, a3d, als, ald, Nn, 1);
    }
    gat_agg_kernel<1, true><<<aggGrid, 256>>>(rowptr, csrc, hbuf, als, ald, b3, bat, pool, Nn);

    // ---- output ----
    out_kernel<<<(NG * FDIM + 255) / 256, 256>>>(pool, cnt, (float*)d_out, NG);

    // NOTE: s2/eFork/eJoin intentionally not destroyed here — destroying a
    // stream/event that participated in an active capture invalidates it, and
    // kernel_launch is invoked only a handful of times (correctness + capture).
}

// round 17
// speedup vs baseline: 1.4090x; 1.1487x over previous
#include <cuda_runtime.h>
#include <cuda_fp16.h>
#include <cstdint>

// ---------------- problem constants ----------------
#define NN      200000
#define NE      1600000
#define NG      5000
#define FDIM    128
#define MAXH    3
#define MAXM    (MAXH*FDIM)   // 384
#define ETOT    (NE + NN)
#define SCAN_B  1024
#define SCAN_NB ((NN + SCAN_B - 1) / SCAN_B)   // 196

// ---------------- scratch ----------------
__device__ __half g_h   [(size_t)NN * MAXM];   // GEMM output features (fp16)
__device__ __half g_feat[(size_t)NN * MAXM];   // layer input features (fp16)
__device__ __half g_xh  [(size_t)NN * FDIM];   // fp16 copy of input x
__device__ __half g_wt  [3 * 384 * 384];       // transposed fp16 weights
__device__ float g_als [(size_t)NN * MAXH];
__device__ float g_ald [(size_t)NN * MAXH];
__device__ float g_pool[(size_t)NG * FDIM];
__device__ int   g_cnt [NG];
__device__ int   g_deg [NN];
__device__ int   g_rowptr[NN + 1];
__device__ int   g_woff[NN];
__device__ int   g_bsum[256];
__device__ int   g_csrc[ETOT];

// ---------------- helpers ----------------
__device__ __forceinline__ float lrelu(float v) { return v > 0.0f ? v : 0.2f * v; }

__device__ __forceinline__ void mma_f16(float* d, const unsigned* a, const unsigned* b) {
    asm volatile(
        "mma.sync.aligned.m16n8k16.row.col.f32.f16.f16.f32 "
        "{%0,%1,%2,%3}, {%4,%5,%6,%7}, {%8,%9}, {%0,%1,%2,%3};"
        : "+f"(d[0]), "+f"(d[1]), "+f"(d[2]), "+f"(d[3])
        : "r"(a[0]), "r"(a[1]), "r"(a[2]), "r"(a[3]), "r"(b[0]), "r"(b[1]));
}

__device__ __forceinline__ void ldsm4(unsigned& r0, unsigned& r1, unsigned& r2, unsigned& r3,
                                      unsigned addr) {
    asm volatile("ldmatrix.sync.aligned.m8n8.x4.shared.b16 {%0,%1,%2,%3}, [%4];"
                 : "=r"(r0), "=r"(r1), "=r"(r2), "=r"(r3) : "r"(addr));
}

#define CP_ASYNC16(saddr, gptr) \
    asm volatile("cp.async.cg.shared.global [%0], [%1], 16;" :: "r"(saddr), "l"(gptr))
#define CP_COMMIT() asm volatile("cp.async.commit_group;")
#define CP_WAIT2()  asm volatile("cp.async.wait_group 2;")

// ---------------- small utility kernels ----------------
__global__ void zero_f(float* p, size_t n) {
    size_t i = (size_t)blockIdx.x * blockDim.x + threadIdx.x;
    size_t stride = (size_t)gridDim.x * blockDim.x;
    for (; i < n; i += stride) p[i] = 0.0f;
}
__global__ void zero_i(int* p, size_t n) {
    size_t i = (size_t)blockIdx.x * blockDim.x + threadIdx.x;
    size_t stride = (size_t)gridDim.x * blockDim.x;
    for (; i < n; i += stride) p[i] = 0;
}
__global__ void cvt_x_kernel(const float* __restrict__ x, __half* __restrict__ xh, size_t n2) {
    size_t i = (size_t)blockIdx.x * blockDim.x + threadIdx.x;
    size_t stride = (size_t)gridDim.x * blockDim.x;
    for (; i < n2; i += stride) {
        float2 v = ((const float2*)x)[i];
        ((__half2*)xh)[i] = __floats2half2_rn(v.x, v.y);
    }
}
__global__ void cvt_w_kernel(const float* __restrict__ W, __half* __restrict__ Wt, int K, int M) {
    int idx = blockIdx.x * blockDim.x + threadIdx.x;
    if (idx >= K * M) return;
    int k = idx / M, m = idx - k * M;
    Wt[(size_t)m * K + k] = __float2half_rn(W[idx]);
}

// ================= CSR construction (by destination) =================
__global__ void deg_kernel(const int* __restrict__ dsts, int E, int Nn, int* __restrict__ deg) {
    int e = blockIdx.x * blockDim.x + threadIdx.x;
    int Et = E + Nn;
    if (e >= Et) return;
    int d = (e < E) ? dsts[e] : (e - E);
    atomicAdd(&deg[d], 1);
}

__global__ void scan1_kernel(const int* __restrict__ deg, int* __restrict__ excl,
                             int* __restrict__ bsum, int n) {
    __shared__ int sm[SCAN_B];
    int t = threadIdx.x;
    int gid = blockIdx.x * SCAN_B + t;
    int v = (gid < n) ? deg[gid] : 0;
    sm[t] = v;
    __syncthreads();
#pragma unroll
    for (int o = 1; o < SCAN_B; o <<= 1) {
        int u = (t >= o) ? sm[t - o] : 0;
        __syncthreads();
        sm[t] += u;
        __syncthreads();
    }
    if (gid < n) excl[gid] = sm[t] - v;
    if (t == SCAN_B - 1) bsum[blockIdx.x] = sm[t];
}

__global__ void scan2_kernel(int* __restrict__ bsum, int nb) {
    __shared__ int sm[256];
    int t = threadIdx.x;
    int v = (t < nb) ? bsum[t] : 0;
    sm[t] = v;
    __syncthreads();
#pragma unroll
    for (int o = 1; o < 256; o <<= 1) {
        int u = (t >= o) ? sm[t - o] : 0;
        __syncthreads();
        sm[t] += u;
        __syncthreads();
    }
    if (t < nb) bsum[t] = sm[t] - v;
}

__global__ void scan3_kernel(int* __restrict__ rowptr, int* __restrict__ woff,
                             const int* __restrict__ bsum, int n, int Et) {
    int gid = blockIdx.x * SCAN_B + threadIdx.x;
    if (gid < n) {
        int v = rowptr[gid] + bsum[gid >> 10];
        rowptr[gid] = v;
        woff[gid] = v;
    }
    if (gid == 0) rowptr[n] = Et;
}

__global__ void scatter_kernel(const int* __restrict__ srcs, const int* __restrict__ dsts,
                               int E, int Nn, int* __restrict__ woff, int* __restrict__ csrc) {
    int e = blockIdx.x * blockDim.x + threadIdx.x;
    int Et = E + Nn;
    if (e >= Et) return;
    int s, d;
    if (e < E) { s = srcs[e]; d = dsts[e]; }
    else       { s = d = e - E; }
    int pos = atomicAdd(&woff[d], 1);
    csrc[pos] = s;
}

// ====== tensor-core GEMM: fp16, 4-stage cp.async pipeline + fused attn dots ======
// C[Nrows,M] = A[Nrows,K] @ Wt[M,K]^T.  CTA 128x128; each CTA's column span is
// exactly one head (head = bn>>7), so complete per-row attention dot products
// are computed in-CTA from fp32 accumulators: butterfly over tg + 4KB smem
// reduction across the 4 N-warps. No atomics.
#define GBM 128
#define GBN 128
#define TST 20
#define STAGE_BYTES (GBM * TST * 4)   // 10240
#define NSTAGE 4
#define GEMM_SMEM (NSTAGE * STAGE_BYTES * 2)   // 81920

__global__ __launch_bounds__(256, 2) void gemm_fp16_kernel(const __half* __restrict__ A,
                                                           const __half* __restrict__ Wt,
                                                           __half* __restrict__ C,
                                                           const float* __restrict__ avs,
                                                           const float* __restrict__ avd,
                                                           float* __restrict__ als,
                                                           float* __restrict__ ald,
                                                           int Nrows, int K, int M, int H) {
    extern __shared__ unsigned smem_dyn[];

    const int bm = blockIdx.y * GBM;
    const int bn = blockIdx.x * GBN;
    const int t  = threadIdx.x;
    const int w  = t >> 5;
    const int l  = t & 31;
    const int g  = l >> 2;
    const int tg = l & 3;
    const int mw = (w & 1) * 64;
    const int nw = (w >> 1) * 32;

    float acc[4][4][4];
#pragma unroll
    for (int i = 0; i < 4; ++i)
#pragma unroll
        for (int j = 0; j < 4; ++j)
#pragma unroll
            for (int q = 0; q < 4; ++q) acc[i][j][q] = 0.0f;

    const int ns = K >> 5;

    const unsigned uA = (unsigned)__cvta_generic_to_shared(smem_dyn);
    const unsigned uB = uA + NSTAGE * STAGE_BYTES;

    const int atile   = l >> 3;
    const int arow0   = mw + (atile & 1) * 8 + (l & 7);
    const int achunk  = atile >> 1;
    const int bsel    = l >> 4;
    const int bchunk  = (l >> 3) & 1;
    const int brow0   = nw + (l & 7);

    auto load_stage = [&](int s, int buf) {
        int k0 = s << 5;
#pragma unroll
        for (int i = 0; i < 2; ++i) {
            int lin = i * 256 + t;
            int r = lin >> 2;
            int seg = lin & 3;
            int ar = bm + r;
            if (ar >= Nrows) ar = Nrows - 1;
            unsigned sa = uA + (unsigned)(buf * STAGE_BYTES + r * 80 + seg * 16);
            CP_ASYNC16(sa, &A[(size_t)ar * K + k0 + seg * 8]);
        }
#pragma unroll
        for (int i = 0; i < 2; ++i) {
            int lin = i * 256 + t;
            int r = lin >> 2;
            int seg = lin & 3;
            unsigned sa = uB + (unsigned)(buf * STAGE_BYTES + r * 80 + seg * 16);
            CP_ASYNC16(sa, &Wt[(size_t)(bn + r) * K + k0 + seg * 8]);
        }
    };

    int pre = ns < 3 ? ns : 3;
    for (int s = 0; s < pre; ++s) { load_stage(s, s); CP_COMMIT(); }

    for (int s = 0; s < ns; ++s) {
        CP_WAIT2();
        __syncthreads();

        if (s + 3 < ns) load_stage(s + 3, (s + 3) & (NSTAGE - 1));
        CP_COMMIT();

        const int buf = s & (NSTAGE - 1);
        const unsigned bufA = uA + (unsigned)(buf * STAGE_BYTES);
        const unsigned bufB = uB + (unsigned)(buf * STAGE_BYTES);

#pragma unroll
        for (int ks = 0; ks < 2; ++ks) {
            const int kc2 = ks * 2;
            unsigned bf[4][2];
#pragma unroll
            for (int p = 0; p < 2; ++p) {
                int nf = p * 2 + bsel;
                unsigned addr = bufB + (unsigned)((brow0 + nf * 8) * 80 + (kc2 + bchunk) * 16);
                ldsm4(bf[p * 2][0], bf[p * 2][1], bf[p * 2 + 1][0], bf[p * 2 + 1][1], addr);
            }
            unsigned af[4][4];
#pragma unroll
            for (int mf = 0; mf < 4; ++mf) {
                unsigned addr = bufA + (unsigned)((arow0 + mf * 16) * 80 + (kc2 + achunk) * 16);
                ldsm4(af[mf][0], af[mf][1], af[mf][2], af[mf][3], addr);
            }
#pragma unroll
            for (int mf = 0; mf < 4; ++mf)
#pragma unroll
                for (int nf = 0; nf < 4; ++nf)
                    mma_f16(acc[mf][nf], af[mf], bf[nf]);
        }
    }

    // ---- attn dot partials from fp32 accumulators (acc still live) ----
    float ps_lo[4], ps_hi[4], pd_lo[4], pd_hi[4];
#pragma unroll
    for (int mf = 0; mf < 4; ++mf) {
        float sl = 0.f, sh = 0.f, dl = 0.f, dh = 0.f;
#pragma unroll
        for (int nf = 0; nf < 4; ++nf) {
            int col = bn + nw + nf * 8 + 2 * tg;
            float as0 = avs[col], as1 = avs[col + 1];
            float ad0 = avd[col], ad1 = avd[col + 1];
            sl += acc[mf][nf][0] * as0 + acc[mf][nf][1] * as1;
            sh += acc[mf][nf][2] * as0 + acc[mf][nf][3] * as1;
            dl += acc[mf][nf][0] * ad0 + acc[mf][nf][1] * ad1;
            dh += acc[mf][nf][2] * ad0 + acc[mf][nf][3] * ad1;
        }
#pragma unroll
        for (int o = 1; o < 4; o <<= 1) {
            sl += __shfl_xor_sync(0xffffffffu, sl, o);
            sh += __shfl_xor_sync(0xffffffffu, sh, o);
            dl += __shfl_xor_sync(0xffffffffu, dl, o);
            dh += __shfl_xor_sync(0xffffffffu, dh, o);
        }
        ps_lo[mf] = sl; ps_hi[mf] = sh; pd_lo[mf] = dl; pd_hi[mf] = dh;
    }

    // ---- C store (fp16, guarded rows) ----
#pragma unroll
    for (int mf = 0; mf < 4; ++mf)
#pragma unroll
        for (int nf = 0; nf < 4; ++nf) {
            int row = bm + mw + mf * 16 + g;
            int col = bn + nw + nf * 8 + 2 * tg;
            if (row < Nrows)
                *(__half2*)&C[(size_t)row * M + col] =
                    __floats2half2_rn(acc[mf][nf][0], acc[mf][nf][1]);
            if (row + 8 < Nrows)
                *(__half2*)&C[(size_t)(row + 8) * M + col] =
                    __floats2half2_rn(acc[mf][nf][2], acc[mf][nf][3]);
        }

    // ---- cross-N-warp reduction in smem (reuse pipeline smem) ----
    __syncthreads();   // all warps done reading pipeline buffers
    float* sm_s = (float*)smem_dyn;          // [128][4]
    float* sm_d = sm_s + 512;                // [128][4]
    const int nwidx = w >> 1;
    if (tg == 0) {
#pragma unroll
        for (int mf = 0; mf < 4; ++mf) {
            int r0 = mw + mf * 16 + g;
            sm_s[r0 * 4 + nwidx] = ps_lo[mf];
            sm_s[(r0 + 8) * 4 + nwidx] = ps_hi[mf];
            sm_d[r0 * 4 + nwidx] = pd_lo[mf];
            sm_d[(r0 + 8) * 4 + nwidx] = pd_hi[mf];
        }
    }
    __syncthreads();
    if (t < GBM) {
        int grow = bm + t;
        if (grow < Nrows) {
            const int head = bn >> 7;
            float s = (sm_s[t * 4 + 0] + sm_s[t * 4 + 1]) + (sm_s[t * 4 + 2] + sm_s[t * 4 + 3]);
            float d = (sm_d[t * 4 + 0] + sm_d[t * 4 + 1]) + (sm_d[t * 4 + 2] + sm_d[t * 4 + 3]);
            als[(size_t)grow * H + head] = s;
            ald[(size_t)grow * H + head] = d;
        }
    }
}

// ========== fused GAT aggregation (warp/node, CSR, combined heads, 2-edge SWP) ====
template<int H, bool POOL>
__global__ void gat_agg_kernel(const int* __restrict__ rowptr, const int* __restrict__ csrc,
                               const __half* __restrict__ hbuf,
                               const float* __restrict__ als, const float* __restrict__ ald,
                               const float* __restrict__ bias,
                               const int* __restrict__ batch,
                               void* __restrict__ outp, int Nn) {
    int w = (blockIdx.x * blockDim.x + threadIdx.x) >> 5;
    int lane = threadIdx.x & 31;
    if (w >= Nn) return;
    int beg = rowptr[w], end = rowptr[w + 1];
    const int M = H * FDIM;

    float aldv = (lane < H) ? ald[(size_t)w * H + lane] : 0.0f;
    float den[H];
    float4 acc[H];
#pragma unroll
    for (int h = 0; h < H; ++h) { den[h] = 0.0f; acc[h] = make_float4(0, 0, 0, 0); }

    int i = beg;
    for (; i + 2 <= end; i += 2) {
        int s0 = csrc[i], s1 = csrc[i + 1];
        const uint2* hp0 = (const uint2*)(hbuf + (size_t)s0 * M) + lane;
        const uint2* hp1 = (const uint2*)(hbuf + (size_t)s1 * M) + lane;
        uint2 r0[H], r1[H];
#pragma unroll
        for (int h = 0; h < H; ++h) { r0[h] = hp0[h * 32]; r1[h] = hp1[h * 32]; }
        float as0 = (lane < H) ? als[(size_t)s0 * H + lane] : 0.0f;
        float as1 = (lane < H) ? als[(size_t)s1 * H + lane] : 0.0f;
        float e0 = expf(lrelu(as0 + aldv));
        float e1 = expf(lrelu(as1 + aldv));
#pragma unroll
        for (int h = 0; h < H; ++h) {
            float ex0 = __shfl_sync(0xffffffffu, e0, h);
            float ex1 = __shfl_sync(0xffffffffu, e1, h);
            float2 fa = __half22float2(*(__half2*)&r0[h].x);
            float2 fb = __half22float2(*(__half2*)&r0[h].y);
            float2 ga = __half22float2(*(__half2*)&r1[h].x);
            float2 gb = __half22float2(*(__half2*)&r1[h].y);
            acc[h].x = fmaf(ex0, fa.x, fmaf(ex1, ga.x, acc[h].x));
            acc[h].y = fmaf(ex0, fa.y, fmaf(ex1, ga.y, acc[h].y));
            acc[h].z = fmaf(ex0, fb.x, fmaf(ex1, gb.x, acc[h].z));
            acc[h].w = fmaf(ex0, fb.y, fmaf(ex1, gb.y, acc[h].w));
            den[h] += ex0 + ex1;
        }
    }
    if (i < end) {
        int s0 = csrc[i];
        const uint2* hp0 = (const uint2*)(hbuf + (size_t)s0 * M) + lane;
        uint2 r0[H];
#pragma unroll
        for (int h = 0; h < H; ++h) r0[h] = hp0[h * 32];
        float as0 = (lane < H) ? als[(size_t)s0 * H + lane] : 0.0f;
        float e0 = expf(lrelu(as0 + aldv));
#pragma unroll
        for (int h = 0; h < H; ++h) {
            float ex0 = __shfl_sync(0xffffffffu, e0, h);
            float2 fa = __half22float2(*(__half2*)&r0[h].x);
            float2 fb = __half22float2(*(__half2*)&r0[h].y);
            acc[h].x = fmaf(ex0, fa.x, acc[h].x);
            acc[h].y = fmaf(ex0, fa.y, acc[h].y);
            acc[h].z = fmaf(ex0, fb.x, acc[h].z);
            acc[h].w = fmaf(ex0, fb.y, acc[h].w);
            den[h] += ex0;
        }
    }

    if (POOL) {
        float* outf = (float*)outp;
        float r = 1.0f / (den[0] + 1e-16f);
        float4 bv = *(const float4*)&bias[lane * 4];
        float4 v;
        v.x = lrelu(acc[0].x * r + bv.x);
        v.y = lrelu(acc[0].y * r + bv.y);
        v.z = lrelu(acc[0].z * r + bv.z);
        v.w = lrelu(acc[0].w * r + bv.w);
        float4* p = (float4*)(outf + (size_t)batch[w] * FDIM) + lane;
        asm volatile("red.global.add.v4.f32 [%0], {%1,%2,%3,%4};"
                     :: "l"(p), "f"(v.x), "f"(v.y), "f"(v.z), "f"(v.w) : "memory");
    } else {
        __half* op = (__half*)outp + (size_t)w * M;
#pragma unroll
        for (int h = 0; h < H; ++h) {
            float r = 1.0f / (den[h] + 1e-16f);
            float4 bv = *(const float4*)&bias[h * FDIM + lane * 4];
            __half2 p0 = __floats2half2_rn(lrelu(acc[h].x * r + bv.x),
                                           lrelu(acc[h].y * r + bv.y));
            __half2 p1 = __floats2half2_rn(lrelu(acc[h].z * r + bv.z),
                                           lrelu(acc[h].w * r + bv.w));
            *(uint2*)&op[h * FDIM + lane * 4] =
                make_uint2(*(unsigned*)&p0, *(unsigned*)&p1);
        }
    }
}

// ---------------- pooling epilogue ----------------
__global__ void count_kernel(const int* __restrict__ batch, int* __restrict__ cnt, int Nn) {
    int n = blockIdx.x * blockDim.x + threadIdx.x;
    if (n < Nn) atomicAdd(&cnt[batch[n]], 1);
}
__global__ void out_kernel(const float* __restrict__ pool, const int* __restrict__ cnt,
                           float* __restrict__ out, int G) {
    int i = blockIdx.x * blockDim.x + threadIdx.x;
    if (i >= G * FDIM) return;
    int g = i >> 7;
    float c = (float)max(cnt[g], 1);
    out[i] = pool[i] / c;
}

// ---------------- host orchestration ----------------
extern "C" void kernel_launch(void* const* d_in, const int* in_sizes, int n_in,
                              void* d_out, int out_size) {
    const float* x   = (const float*)d_in[0];
    const int*   ei  = (const int*)d_in[1];
    const int*   bat = (const int*)d_in[2];
    const float* W1  = (const float*)d_in[3];
    const float* a1s = (const float*)d_in[4];
    const float* a1d = (const float*)d_in[5];
    const float* b1  = (const float*)d_in[6];
    const float* W2  = (const float*)d_in[7];
    const float* a2s = (const float*)d_in[8];
    const float* a2d = (const float*)d_in[9];
    const float* b2  = (const float*)d_in[10];
    const float* W3  = (const float*)d_in[11];
    const float* a3s = (const float*)d_in[12];
    const float* a3d = (const float*)d_in[13];
    const float* b3  = (const float*)d_in[14];

    int Nn = in_sizes[0] / FDIM;     // 200000
    int E  = in_sizes[1] / 2;        // 1600000
    int Et = E + Nn;
    const int* srcs = ei;
    const int* dsts = ei + E;

    __half *hbuf, *feat, *xh, *wt;
    float *als, *ald, *pool;
    int *cnt, *deg, *rowptr, *woff, *bsum, *csrc;
    cudaGetSymbolAddress((void**)&hbuf,   g_h);
    cudaGetSymbolAddress((void**)&feat,   g_feat);
    cudaGetSymbolAddress((void**)&xh,     g_xh);
    cudaGetSymbolAddress((void**)&wt,     g_wt);
    cudaGetSymbolAddress((void**)&als,    g_als);
    cudaGetSymbolAddress((void**)&ald,    g_ald);
    cudaGetSymbolAddress((void**)&pool,   g_pool);
    cudaGetSymbolAddress((void**)&cnt,    g_cnt);
    cudaGetSymbolAddress((void**)&deg,    g_deg);
    cudaGetSymbolAddress((void**)&rowptr, g_rowptr);
    cudaGetSymbolAddress((void**)&woff,   g_woff);
    cudaGetSymbolAddress((void**)&bsum,   g_bsum);
    cudaGetSymbolAddress((void**)&csrc,   g_csrc);

    cudaFuncSetAttribute(gemm_fp16_kernel,
                         cudaFuncAttributeMaxDynamicSharedMemorySize, GEMM_SMEM);

    __half* wt1 = wt;                    // [384][128]
    __half* wt2 = wt + 384 * 384;        // [384][384]
    __half* wt3 = wt + 2 * 384 * 384;    // [128][384]

    const unsigned aggGrid = (unsigned)(((size_t)Nn * 32 + 255) / 256);
    const int nbm = (Nn + GBM - 1) / GBM;    // 1563

    // ---- side stream for independent prework (fork/join, capture-legal) ----
    cudaStream_t s2;
    cudaStreamCreateWithFlags(&s2, cudaStreamNonBlocking);
    cudaEvent_t eFork, eJoin;
    cudaEventCreateWithFlags(&eFork, cudaEventDisableTiming);
    cudaEventCreateWithFlags(&eJoin, cudaEventDisableTiming);

    cudaEventRecord(eFork, 0);
    cudaStreamWaitEvent(s2, eFork, 0);

    // ---- side stream: CSR build + non-critical converts + pool prep ----
    zero_i<<<512, 256, 0, s2>>>(deg, (size_t)Nn);
    deg_kernel<<<(Et + 255) / 256, 256, 0, s2>>>(dsts, E, Nn, deg);
    scan1_kernel<<<SCAN_NB, SCAN_B, 0, s2>>>(deg, rowptr, bsum, Nn);
    scan2_kernel<<<1, 256, 0, s2>>>(bsum, SCAN_NB);
    scan3_kernel<<<SCAN_NB, SCAN_B, 0, s2>>>(rowptr, woff, bsum, Nn, Et);
    scatter_kernel<<<(Et + 255) / 256, 256, 0, s2>>>(srcs, dsts, E, Nn, woff, csrc);
    cvt_w_kernel<<<(384 * 384 + 255) / 256, 256, 0, s2>>>(W2, wt2, 384, 384);
    cvt_w_kernel<<<(384 * 128 + 255) / 256, 256, 0, s2>>>(W3, wt3, 384, 128);
    zero_f<<<512, 256, 0, s2>>>(pool, (size_t)NG * FDIM);
    zero_i<<<32, 256, 0, s2>>>(cnt, (size_t)NG);
    count_kernel<<<(Nn + 255) / 256, 256, 0, s2>>>(bat, cnt, Nn);
    cudaEventRecord(eJoin, s2);

    // ---- main stream: layer-1 critical path ----
    cvt_x_kernel<<<2048, 256>>>(x, xh, (size_t)Nn * FDIM / 2);
    cvt_w_kernel<<<(128 * 384 + 255) / 256, 256>>>(W1, wt1, 128, 384);
    {
        dim3 ggrid(384 / GBN, nbm);                                   // <- profiled window
        gemm_fp16_kernel<<<ggrid, 256, GEMM_SMEM>>>(xh, wt1, hbuf, a1s, a1d, als, ald,
                                                    Nn, 128, 384, 3);
    }
    cudaStreamWaitEvent(0, eJoin, 0);   // join: agg needs rowptr/csrc; gemm2 needs wt2
    gat_agg_kernel<3, false><<<aggGrid, 256>>>(rowptr, csrc, hbuf, als, ald, b1, bat, feat, Nn);

    // ---- layer 2: 384 -> 3x128 ----
    {
        dim3 ggrid(384 / GBN, nbm);
        gemm_fp16_kernel<<<ggrid, 256, GEMM_SMEM>>>(feat, wt2, hbuf, a2s, a2d, als, ald,
                                                    Nn, 384, 384, 3);
    }
    gat_agg_kernel<3, false><<<aggGrid, 256>>>(rowptr, csrc, hbuf, als, ald, b2, bat, feat, Nn);

    // ---- layer 3: 384 -> 1x128 + fused pooling scatter ----
    {
        dim3 ggrid(128 / GBN, nbm);
        gemm_fp16_kernel<<<ggrid, 256, GEMM_SMEM>>>(feat, wt3, hbuf, a3s, a3d, als, ald,
                                                    Nn, 384, 128, 1);
    }
    gat_agg_kernel<1, true><<<aggGrid, 256>>>(rowptr, csrc, hbuf, als, ald, b3, bat, pool, Nn);

    // ---- output ----
    out_kernel<<<(NG * FDIM + 255) / 256, 256>>>(pool, cnt, (float*)d_out, NG);

    // NOTE: s2/eFork/eJoin intentionally not destroyed here — destroying a
    // stream/event that participated in an active capture invalidates it, and
    // kernel_launch is invoked only a handful of times (correctness + capture).
}